// round 8
// baseline (speedup 1.0000x reference)
#include <cuda_runtime.h>
#include <cstdint>

// GNN layer, all GEMMs on tf32 mma.sync m16n8k8:
//   A|B = nf @ [We1_rows0:128 | We1_rows128:256]   (per node, precomputed)
//   edge (fused): Cfrag = ef @ We1_ef (mma, M=32, once per edge);
//                 expand: h_fwd/h_rev = rna(leaky(C + A[s]+B[d] / A[d]+B[s]))
//                         -> smem in FRAGMENT-MAJOR layout;
//                 msg = h @ We2 (mma, 2Mx4N warp grid, LDS.128 A-frags,
//                         paired-kt uint4 weight frags); red.global.add.v4 into red[dst]
//   node (fused): hn = leaky([nf|red] @ Wn1) -> smem; out = hn @ Wn2
//
// h fragment-major layout: off(r,k) = r*272 + ((k&7)>>1)*68 + (k>>3)*2 + (k&1)
//   -> lane(fg,fc) reads uint4 at r*272 + fc*68 + ktp*4 = frags for kt-pair {2ktp, 2ktp+1}
//   row stride 272: (272/4)%8 == 4 -> 8-lane LDS.128 phases hit all 32 banks (conflict-free)

constexpr int NN_MAX = 100000;
constexpr int NE_MAX = 500000;
constexpr float NEG = 0.01f;

__device__ __align__(128) float g_AB[(size_t)NN_MAX * 512];
__device__ __align__(128) float g_red[(size_t)NN_MAX * 128];
__device__ __align__(128) float g_fA[128 * 256];
__device__ __align__(128) float g_fB[128 * 256];
__device__ __align__(128) float g_fC[64 * 256];
__device__ __align__(128) float g_fN1[256 * 256];
__device__ __align__(128) float g_fN2[256 * 128];
__device__ __align__(128) float g_fE2[256 * 128];   // paired-kt layout

__device__ __forceinline__ float lky(float x) { return x >= 0.0f ? x : NEG * x; }

__device__ __forceinline__ float rna_tf32(float x) {
    float r; asm("cvt.rna.tf32.f32 %0, %1;" : "=f"(r) : "f"(x)); return r;
}

__device__ __forceinline__ void red_add_v4(float* addr, float a, float b, float c, float d) {
    asm volatile("red.global.add.v4.f32 [%0], {%1,%2,%3,%4};"
                 :: "l"(addr), "f"(a), "f"(b), "f"(c), "f"(d) : "memory");
}

#define MMA_TF32(D0, D1, D2, D3, AV, AV8, BV)                                   \
    asm volatile("mma.sync.aligned.m16n8k8.row.col.f32.tf32.tf32.f32 "          \
                 "{%0,%1,%2,%3}, {%4,%5,%6,%7}, {%8,%9}, {%0,%1,%2,%3};"        \
                 : "+f"(D0), "+f"(D1), "+f"(D2), "+f"(D3)                       \
                 : "r"((AV).x), "r"((AV8).x), "r"((AV).y), "r"((AV8).y),        \
                   "r"((BV).x), "r"((BV).y))

#define MMA_TF32S(D0, D1, D2, D3, AX, A8X, AY, A8Y, BX, BY)                     \
    asm volatile("mma.sync.aligned.m16n8k8.row.col.f32.tf32.tf32.f32 "          \
                 "{%0,%1,%2,%3}, {%4,%5,%6,%7}, {%8,%9}, {%0,%1,%2,%3};"        \
                 : "+f"(D0), "+f"(D1), "+f"(D2), "+f"(D3)                       \
                 : "r"(AX), "r"(A8X), "r"(AY), "r"(A8Y), "r"(BX), "r"(BY))

// ---- merged one-time setup ----
template <int K, int N>
__device__ __forceinline__ void do_frag(int fi, const float* __restrict__ W,
                                        float* __restrict__ Wf) {
    if (fi >= K * N) return;
    int j = fi & 1;
    int lane = (fi >> 1) & 31;
    int kt = (fi >> 6) % (K / 8);
    int ntg = fi / (64 * (K / 8));
    int fc = lane & 3, fg = lane >> 2;
    Wf[fi] = rna_tf32(W[(kt * 8 + 2 * fc + j) * N + ntg * 8 + fg]);
}

// paired-kt fragment layout (K=256, N=128):
// Wf[((ntg*16 + ktp)*128) + lane*4 + ktin*2 + j]
__device__ __forceinline__ void do_frag_p2(int fi, const float* __restrict__ W,
                                           float* __restrict__ Wf) {
    if (fi >= 256 * 128) return;
    int j = fi & 1;
    int ktin = (fi >> 1) & 1;
    int lane = (fi >> 2) & 31;
    int ktp = (fi >> 7) & 15;
    int ntg = fi >> 11;
    int fc = lane & 3, fg = lane >> 2;
    int k = (ktp * 2 + ktin) * 8 + 2 * fc + j;
    Wf[fi] = rna_tf32(W[k * 128 + ntg * 8 + fg]);
}

__global__ void setup_all(const float* __restrict__ We1, const float* __restrict__ We2,
                          const float* __restrict__ Wn1, const float* __restrict__ Wn2,
                          float4* __restrict__ red4, int n4,
                          float* fA, float* fB, float* fC,
                          float* fN1, float* fN2, float* fE2) {
    int tid = blockIdx.x * 256 + threadIdx.x;
    if (tid < n4) red4[tid] = make_float4(0.f, 0.f, 0.f, 0.f);
    do_frag<128, 256>(tid, We1, fA);
    do_frag<128, 256>(tid, We1 + 128 * 256, fB);
    do_frag<64, 256>(tid, We1 + 256 * 256, fC);
    do_frag<256, 256>(tid, Wn1, fN1);
    do_frag<256, 128>(tid, Wn2, fN2);
    do_frag_p2(tid, We2, fE2);
}

// ---- generic tf32 mma GEMM, 1(M)x8(N) warp grid, tile M=64 ----
template <int K, int N>
__global__ void __launch_bounds__(256, 2)
mma_gemm(const float* __restrict__ X1, const float* __restrict__ Wf,
         float* __restrict__ out, int M, int ostride) {
    constexpr int ST = K + 8;
    constexpr int KT = K / 8;
    constexpr int NT = N / 64;
    constexpr int K4 = K / 4;
    extern __shared__ float xs[];

    const int tid = threadIdx.x;
    const int row0 = blockIdx.x * 64;

    for (int idx = tid; idx < 64 * K4; idx += 256) {
        int r = idx / K4, k4 = idx % K4;
        int row = row0 + r;
        float4 v = make_float4(0.f, 0.f, 0.f, 0.f);
        if (row < M) v = ((const float4*)X1)[(size_t)row * K4 + k4];
        v.x = rna_tf32(v.x); v.y = rna_tf32(v.y);
        v.z = rna_tf32(v.z); v.w = rna_tf32(v.w);
        *(float4*)&xs[r * ST + k4 * 4] = v;
    }
    __syncthreads();

    const int w = tid >> 5, lane = tid & 31;
    const int fg = lane >> 2, fc = lane & 3;

    float d0[4][NT], d1[4][NT], d2[4][NT], d3[4][NT];
#pragma unroll
    for (int mt = 0; mt < 4; mt++)
#pragma unroll
        for (int nt = 0; nt < NT; nt++) { d0[mt][nt] = d1[mt][nt] = d2[mt][nt] = d3[mt][nt] = 0.f; }

    for (int kt = 0; kt < KT; kt++) {
        uint2 a[8];
#pragma unroll
        for (int j = 0; j < 8; j++)
            a[j] = *(const uint2*)&xs[(fg + j * 8) * ST + kt * 8 + 2 * fc];
#pragma unroll
        for (int nt = 0; nt < NT; nt++) {
            uint2 bv = __ldg((const uint2*)&Wf[(size_t)((w * NT + nt) * KT + kt) * 64 + lane * 2]);
#pragma unroll
            for (int mt = 0; mt < 4; mt++)
                MMA_TF32(d0[mt][nt], d1[mt][nt], d2[mt][nt], d3[mt][nt],
                         a[2 * mt], a[2 * mt + 1], bv);
        }
    }

#pragma unroll
    for (int mt = 0; mt < 4; mt++) {
#pragma unroll
        for (int nt = 0; nt < NT; nt++) {
            int row = row0 + mt * 16 + fg;
            int col = w * (NT * 8) + nt * 8 + 2 * fc;
            if (row < M)     *(float2*)&out[(size_t)row * ostride + col]       = make_float2(d0[mt][nt], d1[mt][nt]);
            if (row + 8 < M) *(float2*)&out[(size_t)(row + 8) * ostride + col] = make_float2(d2[mt][nt], d3[mt][nt]);
        }
    }
}

// ---- fused edge kernel: tile = 32 edges -> 64 edge-dir rows ----
constexpr int HROW = 272;                 // fragment-major row stride (floats)
constexpr int SM_EDGE = 64 * HROW * 4;    // 69632 B

__global__ void __launch_bounds__(256, 3)
edge_fused(const float* __restrict__ AB, const float* __restrict__ ef,
           const float* __restrict__ fC, const float* __restrict__ fE2,
           const int* __restrict__ src, const int* __restrict__ dst,
           float* __restrict__ red, int E) {
    extern __shared__ float hs[];   // 64 * 272 fragment-major
    __shared__ int ss[64], dds[64];

    const int tid = threadIdx.x;
    const int t = blockIdx.x;

    if (tid < 64) {
        int er = tid >> 1;
        bool rev = tid & 1;
        int e = t * 32 + er;
        int sv = -1, dv = -1;
        if (e < E) { sv = src[e]; dv = dst[e]; }
        ss[tid]  = rev ? dv : sv;
        dds[tid] = rev ? sv : dv;
    }
    __syncthreads();

    const int w = tid >> 5, lane = tid & 31;
    const int fg = lane >> 2, fc = lane & 3;

    // ef offsets for this thread's 4 fragment edge-rows (M=32 C tile)
    int eo[4];
#pragma unroll
    for (int j = 0; j < 4; j++) {
        int e = t * 32 + fg + j * 8;
        if (e >= E) e = 0;
        eo[j] = e * 64;
    }

    // ---- phase 1: C mma (M=32, K=64) once per edge; expand to both dirs ----
    // warp w owns h-k columns [w*32, w*32+32)
#pragma unroll
    for (int ch = 0; ch < 2; ch++) {
        float d0[2][2], d1[2][2], d2[2][2], d3[2][2];
#pragma unroll
        for (int mt = 0; mt < 2; mt++)
#pragma unroll
            for (int nt = 0; nt < 2; nt++) { d0[mt][nt] = d1[mt][nt] = d2[mt][nt] = d3[mt][nt] = 0.f; }

#pragma unroll
        for (int kt = 0; kt < 8; kt++) {
            uint2 a[4];
#pragma unroll
            for (int j = 0; j < 4; j++)
                a[j] = __ldg((const uint2*)&ef[eo[j] + kt * 8 + 2 * fc]);
#pragma unroll
            for (int nt = 0; nt < 2; nt++) {
                int ntg = w * 4 + ch * 2 + nt;
                uint2 bv = __ldg((const uint2*)&fC[(size_t)(ntg * 8 + kt) * 64 + lane * 2]);
#pragma unroll
                for (int mt = 0; mt < 2; mt++)
                    MMA_TF32(d0[mt][nt], d1[mt][nt], d2[mt][nt], d3[mt][nt],
                             a[2 * mt], a[2 * mt + 1], bv);
            }
        }

        // expand each C element into fwd + rev h rows (fragment-major write)
#pragma unroll
        for (int mt = 0; mt < 2; mt++) {
#pragma unroll
            for (int nt = 0; nt < 2; nt++) {
                int col = w * 32 + (ch * 2 + nt) * 8 + 2 * fc;
                int pos = fc * 68 + (col >> 3) * 2;     // fragment-major in-row offset
#pragma unroll
                for (int half = 0; half < 2; half++) {
                    int er = mt * 16 + fg + half * 8;
                    float cx = half ? d2[mt][nt] : d0[mt][nt];
                    float cy = half ? d3[mt][nt] : d1[mt][nt];
#pragma unroll
                    for (int dir = 0; dir < 2; dir++) {
                        int hr = 2 * er + dir;
                        int s = ss[hr], d = dds[hr];
                        float2 h = make_float2(0.f, 0.f);
                        if (s >= 0) {
                            float2 av = *(const float2*)&AB[(size_t)s * 512 + col];
                            float2 bv = *(const float2*)&AB[(size_t)d * 512 + 256 + col];
                            h.x = rna_tf32(lky(cx + av.x + bv.x));
                            h.y = rna_tf32(lky(cy + av.y + bv.y));
                        }
                        *(float2*)&hs[hr * HROW + pos] = h;
                    }
                }
            }
        }
    }
    __syncthreads();

    // ---- phase 2: msg = h @ We2; 2(M) x 4(N) warp grid, Mw=32, Nw=32 ----
    const int wm = w & 1, wc = w >> 1;
    const int rb = wm * 32;

    float e0[2][4], e1[2][4], e2[2][4], e3[2][4];
#pragma unroll
    for (int mt = 0; mt < 2; mt++)
#pragma unroll
        for (int nt = 0; nt < 4; nt++) { e0[mt][nt] = e1[mt][nt] = e2[mt][nt] = e3[mt][nt] = 0.f; }

#pragma unroll 4
    for (int ktp = 0; ktp < 16; ktp++) {
        uint4 a[4];
#pragma unroll
        for (int j = 0; j < 4; j++)
            a[j] = *(const uint4*)&hs[(rb + fg + j * 8) * HROW + fc * 68 + ktp * 4];
#pragma unroll
        for (int nt = 0; nt < 4; nt++) {
            uint4 wv = __ldg((const uint4*)&fE2[(size_t)(((wc * 4 + nt) * 16 + ktp) << 7) + lane * 4]);
            // kt = 2*ktp
            MMA_TF32S(e0[0][nt], e1[0][nt], e2[0][nt], e3[0][nt],
                      a[0].x, a[1].x, a[0].y, a[1].y, wv.x, wv.y);
            MMA_TF32S(e0[1][nt], e1[1][nt], e2[1][nt], e3[1][nt],
                      a[2].x, a[3].x, a[2].y, a[3].y, wv.x, wv.y);
            // kt = 2*ktp + 1
            MMA_TF32S(e0[0][nt], e1[0][nt], e2[0][nt], e3[0][nt],
                      a[0].z, a[1].z, a[0].w, a[1].w, wv.z, wv.w);
            MMA_TF32S(e0[1][nt], e1[1][nt], e2[1][nt], e3[1][nt],
                      a[2].z, a[3].z, a[2].w, a[3].w, wv.z, wv.w);
        }
    }

    // ---- scatter-add (v4 via lane pairing) ----
#pragma unroll
    for (int mt = 0; mt < 2; mt++) {
        int rowA = rb + mt * 16 + fg;
        int dA = dds[rowA];
        int dB = dds[rowA + 8];
#pragma unroll
        for (int nt = 0; nt < 4; nt++) {
            float s0 = __shfl_down_sync(0xffffffffu, e0[mt][nt], 1);
            float s1 = __shfl_down_sync(0xffffffffu, e1[mt][nt], 1);
            float s2 = __shfl_down_sync(0xffffffffu, e2[mt][nt], 1);
            float s3 = __shfl_down_sync(0xffffffffu, e3[mt][nt], 1);
            if ((fc & 1) == 0) {
                int col = wc * 32 + nt * 8 + 2 * fc;
                if (dA >= 0) red_add_v4(&red[(size_t)dA * 128 + col], e0[mt][nt], e1[mt][nt], s0, s1);
                if (dB >= 0) red_add_v4(&red[(size_t)dB * 128 + col], e2[mt][nt], e3[mt][nt], s2, s3);
            }
        }
    }
}

// ---- fused node MLP: hn = leaky([nf|red] @ Wn1); out = hn @ Wn2 ----
constexpr int EST = 264;
__global__ void __launch_bounds__(256, 2)
node_fused(const float* __restrict__ nf, const float* __restrict__ red,
           const float* __restrict__ fN1, const float* __restrict__ fN2,
           float* __restrict__ out, int M) {
    extern __shared__ float xs[];   // 64 * 264
    const int tid = threadIdx.x;
    const int row0 = blockIdx.x * 64;

    for (int idx = tid; idx < 64 * 64; idx += 256) {
        int r = idx >> 6, k4 = idx & 63;
        int row = row0 + r;
        float4 v = make_float4(0.f, 0.f, 0.f, 0.f);
        if (row < M)
            v = (k4 < 32) ? ((const float4*)nf)[(size_t)row * 32 + k4]
                          : ((const float4*)red)[(size_t)row * 32 + (k4 - 32)];
        v.x = rna_tf32(v.x); v.y = rna_tf32(v.y);
        v.z = rna_tf32(v.z); v.w = rna_tf32(v.w);
        *(float4*)&xs[r * EST + k4 * 4] = v;
    }
    __syncthreads();

    const int w = tid >> 5, lane = tid & 31;
    const int fg = lane >> 2, fc = lane & 3;

    float h0[4][4], h1[4][4], h2[4][4], h3[4][4];
#pragma unroll
    for (int mt = 0; mt < 4; mt++)
#pragma unroll
        for (int nt = 0; nt < 4; nt++) { h0[mt][nt] = h1[mt][nt] = h2[mt][nt] = h3[mt][nt] = 0.f; }

    for (int kt = 0; kt < 32; kt++) {
        uint2 a[8];
#pragma unroll
        for (int j = 0; j < 8; j++)
            a[j] = *(const uint2*)&xs[(fg + j * 8) * EST + kt * 8 + 2 * fc];
#pragma unroll
        for (int nt = 0; nt < 4; nt++) {
            uint2 bv = __ldg((const uint2*)&fN1[(size_t)((w * 4 + nt) * 32 + kt) * 64 + lane * 2]);
#pragma unroll
            for (int mt = 0; mt < 4; mt++)
                MMA_TF32(h0[mt][nt], h1[mt][nt], h2[mt][nt], h3[mt][nt],
                         a[2 * mt], a[2 * mt + 1], bv);
        }
    }
    __syncthreads();

#pragma unroll
    for (int mt = 0; mt < 4; mt++) {
#pragma unroll
        for (int nt = 0; nt < 4; nt++) {
            int row = mt * 16 + fg;
            int col = w * 32 + nt * 8 + 2 * fc;
            *(float2*)&xs[row * EST + col] =
                make_float2(rna_tf32(lky(h0[mt][nt])), rna_tf32(lky(h1[mt][nt])));
            *(float2*)&xs[(row + 8) * EST + col] =
                make_float2(rna_tf32(lky(h2[mt][nt])), rna_tf32(lky(h3[mt][nt])));
        }
    }
    __syncthreads();

    float o0[4][2], o1[4][2], o2[4][2], o3[4][2];
#pragma unroll
    for (int mt = 0; mt < 4; mt++)
#pragma unroll
        for (int nt = 0; nt < 2; nt++) { o0[mt][nt] = o1[mt][nt] = o2[mt][nt] = o3[mt][nt] = 0.f; }

    for (int kt = 0; kt < 32; kt++) {
        uint2 a[8];
#pragma unroll
        for (int j = 0; j < 8; j++)
            a[j] = *(const uint2*)&xs[(fg + j * 8) * EST + kt * 8 + 2 * fc];
#pragma unroll
        for (int nt = 0; nt < 2; nt++) {
            uint2 bv = __ldg((const uint2*)&fN2[(size_t)((w * 2 + nt) * 32 + kt) * 64 + lane * 2]);
#pragma unroll
            for (int mt = 0; mt < 4; mt++)
                MMA_TF32(o0[mt][nt], o1[mt][nt], o2[mt][nt], o3[mt][nt],
                         a[2 * mt], a[2 * mt + 1], bv);
        }
    }

#pragma unroll
    for (int mt = 0; mt < 4; mt++) {
#pragma unroll
        for (int nt = 0; nt < 2; nt++) {
            int row = row0 + mt * 16 + fg;
            int col = w * 16 + nt * 8 + 2 * fc;
            if (row < M)     *(float2*)&out[(size_t)row * 128 + col]       = make_float2(o0[mt][nt], o1[mt][nt]);
            if (row + 8 < M) *(float2*)&out[(size_t)(row + 8) * 128 + col] = make_float2(o2[mt][nt], o3[mt][nt]);
        }
    }
}

extern "C" void kernel_launch(void* const* d_in, const int* in_sizes, int n_in,
                              void* d_out, int out_size) {
    const float* nf  = (const float*)d_in[0];
    const float* ef  = (const float*)d_in[1];
    const int*   src = (const int*)d_in[2];
    const int*   dst = (const int*)d_in[3];
    const float* We1 = (const float*)d_in[4];   // (320, 256)
    const float* We2 = (const float*)d_in[5];   // (256, 128)
    const float* Wn1 = (const float*)d_in[6];   // (256, 256)
    const float* Wn2 = (const float*)d_in[7];   // (256, 128)

    const int N = in_sizes[0] / 128;
    const int E = in_sizes[2];

    float *AB, *red, *fA, *fB, *fC, *fN1, *fN2, *fE2;
    cudaGetSymbolAddress((void**)&AB, g_AB);
    cudaGetSymbolAddress((void**)&red, g_red);
    cudaGetSymbolAddress((void**)&fA, g_fA);
    cudaGetSymbolAddress((void**)&fB, g_fB);
    cudaGetSymbolAddress((void**)&fC, g_fC);
    cudaGetSymbolAddress((void**)&fN1, g_fN1);
    cudaGetSymbolAddress((void**)&fN2, g_fN2);
    cudaGetSymbolAddress((void**)&fE2, g_fE2);

    cudaFuncSetAttribute((const void*)edge_fused,
                         cudaFuncAttributeMaxDynamicSharedMemorySize, SM_EDGE);
    cudaFuncSetAttribute((const void*)node_fused,
                         cudaFuncAttributeMaxDynamicSharedMemorySize, 64 * EST * 4);

    // (0) merged one-time setup
    int n4 = N * 128 / 4;
    setup_all<<<(n4 + 255) / 256, 256>>>(We1, We2, Wn1, Wn2,
                                         (float4*)red, n4, fA, fB, fC, fN1, fN2, fE2);

    // (1,2) A|B halves: nf @ We1 halves -> g_AB (row stride 512)
    mma_gemm<128, 256><<<(N + 63) / 64, 256, 64 * 136 * 4>>>(nf, fA, AB, N, 512);
    mma_gemm<128, 256><<<(N + 63) / 64, 256, 64 * 136 * 4>>>(nf, fB, AB + 256, N, 512);

    // (3) fused edge
    edge_fused<<<(E + 31) / 32, 256, SM_EDGE>>>(AB, ef, fC, fE2, src, dst, red, E);

    // (4) fused node MLP
    node_fused<<<(N + 63) / 64, 256, 64 * EST * 4>>>(nf, red, fN1, fN2, (float*)d_out, N);
}

// round 9
// speedup vs baseline: 1.3743x; 1.3743x over previous
#include <cuda_runtime.h>
#include <cstdint>

// GNN layer, all GEMMs on tf32 mma.sync m16n8k8:
//   A|B = nf @ [We1_rows0:128 | We1_rows128:256]   (per node, precomputed)
//   edge (fused): Cfrag = ef @ We1_ef (mma, M=32, once per edge);
//                 expand: h_fwd/h_rev = rna(leaky(C + A[s]+B[d] / A[d]+B[s])) -> smem (row-major);
//                 msg = h @ We2 (mma, 2Mx4N warp grid); red.global.add.v4 into red[dst]
//   node (fused): hn = leaky([nf|red] @ Wn1) -> smem; out = hn @ Wn2
// Weight fragments pre-shuffled (coalesced LDG.64 B-frags):
//   Wf[((ntg*(K/8)+kt)*64 + lane*2 + j)] = rna(W[(kt*8+2*(lane&3)+j)*N + ntg*8 + (lane>>2)])

constexpr int NN_MAX = 100000;
constexpr int NE_MAX = 500000;
constexpr float NEG = 0.01f;

__device__ __align__(128) float g_AB[(size_t)NN_MAX * 512];
__device__ __align__(128) float g_red[(size_t)NN_MAX * 128];
__device__ __align__(128) float g_fA[128 * 256];
__device__ __align__(128) float g_fB[128 * 256];
__device__ __align__(128) float g_fC[64 * 256];
__device__ __align__(128) float g_fN1[256 * 256];
__device__ __align__(128) float g_fN2[256 * 128];
__device__ __align__(128) float g_fE2[256 * 128];

__device__ __forceinline__ float lky(float x) { return x >= 0.0f ? x : NEG * x; }

__device__ __forceinline__ float rna_tf32(float x) {
    float r; asm("cvt.rna.tf32.f32 %0, %1;" : "=f"(r) : "f"(x)); return r;
}

__device__ __forceinline__ void red_add_v4(float* addr, float a, float b, float c, float d) {
    asm volatile("red.global.add.v4.f32 [%0], {%1,%2,%3,%4};"
                 :: "l"(addr), "f"(a), "f"(b), "f"(c), "f"(d) : "memory");
}

#define MMA_TF32(D0, D1, D2, D3, AV, AV8, BV)                                   \
    asm volatile("mma.sync.aligned.m16n8k8.row.col.f32.tf32.tf32.f32 "          \
                 "{%0,%1,%2,%3}, {%4,%5,%6,%7}, {%8,%9}, {%0,%1,%2,%3};"        \
                 : "+f"(D0), "+f"(D1), "+f"(D2), "+f"(D3)                       \
                 : "r"((AV).x), "r"((AV8).x), "r"((AV).y), "r"((AV8).y),        \
                   "r"((BV).x), "r"((BV).y))

// ---- merged one-time setup: zero red + all weight fragment shuffles ----
template <int K, int N>
__device__ __forceinline__ void do_frag(int fi, const float* __restrict__ W,
                                        float* __restrict__ Wf) {
    if (fi >= K * N) return;
    int j = fi & 1;
    int lane = (fi >> 1) & 31;
    int kt = (fi >> 6) % (K / 8);
    int ntg = fi / (64 * (K / 8));
    int fc = lane & 3, fg = lane >> 2;
    Wf[fi] = rna_tf32(W[(kt * 8 + 2 * fc + j) * N + ntg * 8 + fg]);
}

__global__ void setup_all(const float* __restrict__ We1, const float* __restrict__ We2,
                          const float* __restrict__ Wn1, const float* __restrict__ Wn2,
                          float4* __restrict__ red4, int n4,
                          float* fA, float* fB, float* fC,
                          float* fN1, float* fN2, float* fE2) {
    int tid = blockIdx.x * 256 + threadIdx.x;
    if (tid < n4) red4[tid] = make_float4(0.f, 0.f, 0.f, 0.f);
    do_frag<128, 256>(tid, We1, fA);
    do_frag<128, 256>(tid, We1 + 128 * 256, fB);
    do_frag<64, 256>(tid, We1 + 256 * 256, fC);
    do_frag<256, 256>(tid, Wn1, fN1);
    do_frag<256, 128>(tid, Wn2, fN2);
    do_frag<256, 128>(tid, We2, fE2);
}

// ---- generic tf32 mma GEMM, 1(M)x8(N) warp grid, tile M=64 ----
template <int K, int N>
__global__ void __launch_bounds__(256, 2)
mma_gemm(const float* __restrict__ X1, const float* __restrict__ Wf,
         float* __restrict__ out, int M, int ostride) {
    constexpr int ST = K + 8;
    constexpr int KT = K / 8;
    constexpr int NT = N / 64;
    constexpr int K4 = K / 4;
    extern __shared__ float xs[];

    const int tid = threadIdx.x;
    const int row0 = blockIdx.x * 64;

    for (int idx = tid; idx < 64 * K4; idx += 256) {
        int r = idx / K4, k4 = idx % K4;
        int row = row0 + r;
        float4 v = make_float4(0.f, 0.f, 0.f, 0.f);
        if (row < M) v = ((const float4*)X1)[(size_t)row * K4 + k4];
        v.x = rna_tf32(v.x); v.y = rna_tf32(v.y);
        v.z = rna_tf32(v.z); v.w = rna_tf32(v.w);
        *(float4*)&xs[r * ST + k4 * 4] = v;
    }
    __syncthreads();

    const int w = tid >> 5, lane = tid & 31;
    const int fg = lane >> 2, fc = lane & 3;

    float d0[4][NT], d1[4][NT], d2[4][NT], d3[4][NT];
#pragma unroll
    for (int mt = 0; mt < 4; mt++)
#pragma unroll
        for (int nt = 0; nt < NT; nt++) { d0[mt][nt] = d1[mt][nt] = d2[mt][nt] = d3[mt][nt] = 0.f; }

    for (int kt = 0; kt < KT; kt++) {
        uint2 a[8];
#pragma unroll
        for (int j = 0; j < 8; j++)
            a[j] = *(const uint2*)&xs[(fg + j * 8) * ST + kt * 8 + 2 * fc];
#pragma unroll
        for (int nt = 0; nt < NT; nt++) {
            uint2 bv = __ldg((const uint2*)&Wf[(size_t)((w * NT + nt) * KT + kt) * 64 + lane * 2]);
#pragma unroll
            for (int mt = 0; mt < 4; mt++)
                MMA_TF32(d0[mt][nt], d1[mt][nt], d2[mt][nt], d3[mt][nt],
                         a[2 * mt], a[2 * mt + 1], bv);
        }
    }

#pragma unroll
    for (int mt = 0; mt < 4; mt++) {
#pragma unroll
        for (int nt = 0; nt < NT; nt++) {
            int row = row0 + mt * 16 + fg;
            int col = w * (NT * 8) + nt * 8 + 2 * fc;
            if (row < M)     *(float2*)&out[(size_t)row * ostride + col]       = make_float2(d0[mt][nt], d1[mt][nt]);
            if (row + 8 < M) *(float2*)&out[(size_t)(row + 8) * ostride + col] = make_float2(d2[mt][nt], d3[mt][nt]);
        }
    }
}

// ---- fused edge kernel: tile = 32 edges -> 64 edge-dir rows ----
constexpr int EST = 264;
constexpr int SM_EDGE = 64 * EST * 4;   // 67584 B

__global__ void __launch_bounds__(256, 3)
edge_fused(const float* __restrict__ AB, const float* __restrict__ ef,
           const float* __restrict__ fC, const float* __restrict__ fE2,
           const int* __restrict__ src, const int* __restrict__ dst,
           float* __restrict__ red, int E) {
    extern __shared__ float hs[];   // 64 * 264 row-major
    __shared__ int ss[64], dds[64];

    const int tid = threadIdx.x;
    const int t = blockIdx.x;

    if (tid < 64) {
        int er = tid >> 1;
        bool rev = tid & 1;
        int e = t * 32 + er;
        int sv = -1, dv = -1;
        if (e < E) { sv = src[e]; dv = dst[e]; }
        ss[tid]  = rev ? dv : sv;
        dds[tid] = rev ? sv : dv;
    }
    __syncthreads();

    const int w = tid >> 5, lane = tid & 31;
    const int fg = lane >> 2, fc = lane & 3;

    // ef element offsets for this thread's 4 fragment edge-rows (M=32 C tile)
    int eo[4];
#pragma unroll
    for (int j = 0; j < 4; j++) {
        int e = t * 32 + fg + j * 8;
        if (e >= E) e = 0;
        eo[j] = e * 64;
    }

    // ---- phase 1: C mma (M=32, K=64) once per edge, expand to both dirs ----
#pragma unroll
    for (int ch = 0; ch < 2; ch++) {           // per-warp NT=4, chunks of 2
        float d0[2][2], d1[2][2], d2[2][2], d3[2][2];
#pragma unroll
        for (int mt = 0; mt < 2; mt++)
#pragma unroll
            for (int nt = 0; nt < 2; nt++) { d0[mt][nt] = d1[mt][nt] = d2[mt][nt] = d3[mt][nt] = 0.f; }

#pragma unroll
        for (int kt = 0; kt < 8; kt++) {
            uint2 a[4];
#pragma unroll
            for (int j = 0; j < 4; j++)
                a[j] = __ldg((const uint2*)&ef[eo[j] + kt * 8 + 2 * fc]);
#pragma unroll
            for (int nt = 0; nt < 2; nt++) {
                int ntg = w * 4 + ch * 2 + nt;
                uint2 bv = __ldg((const uint2*)&fC[(size_t)(ntg * 8 + kt) * 64 + lane * 2]);
#pragma unroll
                for (int mt = 0; mt < 2; mt++)
                    MMA_TF32(d0[mt][nt], d1[mt][nt], d2[mt][nt], d3[mt][nt],
                             a[2 * mt], a[2 * mt + 1], bv);
            }
        }

        // expand each C element into fwd + rev h rows
#pragma unroll
        for (int mt = 0; mt < 2; mt++) {
#pragma unroll
            for (int nt = 0; nt < 2; nt++) {
                int col = w * 32 + (ch * 2 + nt) * 8 + 2 * fc;
#pragma unroll
                for (int half = 0; half < 2; half++) {
                    int er = mt * 16 + fg + half * 8;          // edge row 0..31
                    float cx = half ? d2[mt][nt] : d0[mt][nt];
                    float cy = half ? d3[mt][nt] : d1[mt][nt];
#pragma unroll
                    for (int dir = 0; dir < 2; dir++) {
                        int hr = 2 * er + dir;
                        int s = ss[hr], d = dds[hr];
                        float2 h = make_float2(0.f, 0.f);
                        if (s >= 0) {
                            float2 av = *(const float2*)&AB[(size_t)s * 512 + col];
                            float2 bv = *(const float2*)&AB[(size_t)d * 512 + 256 + col];
                            h.x = rna_tf32(lky(cx + av.x + bv.x));
                            h.y = rna_tf32(lky(cy + av.y + bv.y));
                        }
                        *(float2*)&hs[hr * EST + col] = h;
                    }
                }
            }
        }
    }
    __syncthreads();

    // ---- phase 2: msg = h @ We2; 2(M) x 4(N) warp grid, Mw=32, Nw=32 ----
    const int wm = w & 1, wc = w >> 1;
    const int rb = wm * 32;

    float e0[2][4], e1[2][4], e2[2][4], e3[2][4];
#pragma unroll
    for (int mt = 0; mt < 2; mt++)
#pragma unroll
        for (int nt = 0; nt < 4; nt++) { e0[mt][nt] = e1[mt][nt] = e2[mt][nt] = e3[mt][nt] = 0.f; }

    for (int kt = 0; kt < 32; kt++) {
        uint2 a[4];
#pragma unroll
        for (int j = 0; j < 4; j++)
            a[j] = *(const uint2*)&hs[(rb + fg + j * 8) * EST + kt * 8 + 2 * fc];
#pragma unroll
        for (int nt = 0; nt < 4; nt++) {
            uint2 bv = __ldg((const uint2*)&fE2[(size_t)((wc * 4 + nt) * 32 + kt) * 64 + lane * 2]);
#pragma unroll
            for (int mt = 0; mt < 2; mt++)
                MMA_TF32(e0[mt][nt], e1[mt][nt], e2[mt][nt], e3[mt][nt],
                         a[2 * mt], a[2 * mt + 1], bv);
        }
    }

    // ---- scatter-add (v4 via lane pairing) ----
#pragma unroll
    for (int mt = 0; mt < 2; mt++) {
        int rowA = rb + mt * 16 + fg;
        int dA = dds[rowA];
        int dB = dds[rowA + 8];
#pragma unroll
        for (int nt = 0; nt < 4; nt++) {
            float s0 = __shfl_down_sync(0xffffffffu, e0[mt][nt], 1);
            float s1 = __shfl_down_sync(0xffffffffu, e1[mt][nt], 1);
            float s2 = __shfl_down_sync(0xffffffffu, e2[mt][nt], 1);
            float s3 = __shfl_down_sync(0xffffffffu, e3[mt][nt], 1);
            if ((fc & 1) == 0) {
                int col = wc * 32 + nt * 8 + 2 * fc;
                if (dA >= 0) red_add_v4(&red[(size_t)dA * 128 + col], e0[mt][nt], e1[mt][nt], s0, s1);
                if (dB >= 0) red_add_v4(&red[(size_t)dB * 128 + col], e2[mt][nt], e3[mt][nt], s2, s3);
            }
        }
    }
}

// ---- fused node MLP: hn = leaky([nf|red] @ Wn1); out = hn @ Wn2 ----
__global__ void __launch_bounds__(256, 2)
node_fused(const float* __restrict__ nf, const float* __restrict__ red,
           const float* __restrict__ fN1, const float* __restrict__ fN2,
           float* __restrict__ out, int M) {
    extern __shared__ float xs[];   // 64 * 264
    const int tid = threadIdx.x;
    const int row0 = blockIdx.x * 64;

    for (int idx = tid; idx < 64 * 64; idx += 256) {
        int r = idx >> 6, k4 = idx & 63;
        int row = row0 + r;
        float4 v = make_float4(0.f, 0.f, 0.f, 0.f);
        if (row < M)
            v = (k4 < 32) ? ((const float4*)nf)[(size_t)row * 32 + k4]
                          : ((const float4*)red)[(size_t)row * 32 + (k4 - 32)];
        v.x = rna_tf32(v.x); v.y = rna_tf32(v.y);
        v.z = rna_tf32(v.z); v.w = rna_tf32(v.w);
        *(float4*)&xs[r * EST + k4 * 4] = v;
    }
    __syncthreads();

    const int w = tid >> 5, lane = tid & 31;
    const int fg = lane >> 2, fc = lane & 3;

    float h0[4][4], h1[4][4], h2[4][4], h3[4][4];
#pragma unroll
    for (int mt = 0; mt < 4; mt++)
#pragma unroll
        for (int nt = 0; nt < 4; nt++) { h0[mt][nt] = h1[mt][nt] = h2[mt][nt] = h3[mt][nt] = 0.f; }

    for (int kt = 0; kt < 32; kt++) {
        uint2 a[8];
#pragma unroll
        for (int j = 0; j < 8; j++)
            a[j] = *(const uint2*)&xs[(fg + j * 8) * EST + kt * 8 + 2 * fc];
#pragma unroll
        for (int nt = 0; nt < 4; nt++) {
            uint2 bv = __ldg((const uint2*)&fN1[(size_t)((w * 4 + nt) * 32 + kt) * 64 + lane * 2]);
#pragma unroll
            for (int mt = 0; mt < 4; mt++)
                MMA_TF32(h0[mt][nt], h1[mt][nt], h2[mt][nt], h3[mt][nt],
                         a[2 * mt], a[2 * mt + 1], bv);
        }
    }
    __syncthreads();

#pragma unroll
    for (int mt = 0; mt < 4; mt++) {
#pragma unroll
        for (int nt = 0; nt < 4; nt++) {
            int row = mt * 16 + fg;
            int col = w * 32 + nt * 8 + 2 * fc;
            *(float2*)&xs[row * EST + col] =
                make_float2(rna_tf32(lky(h0[mt][nt])), rna_tf32(lky(h1[mt][nt])));
            *(float2*)&xs[(row + 8) * EST + col] =
                make_float2(rna_tf32(lky(h2[mt][nt])), rna_tf32(lky(h3[mt][nt])));
        }
    }
    __syncthreads();

    float o0[4][2], o1[4][2], o2[4][2], o3[4][2];
#pragma unroll
    for (int mt = 0; mt < 4; mt++)
#pragma unroll
        for (int nt = 0; nt < 2; nt++) { o0[mt][nt] = o1[mt][nt] = o2[mt][nt] = o3[mt][nt] = 0.f; }

    for (int kt = 0; kt < 32; kt++) {
        uint2 a[8];
#pragma unroll
        for (int j = 0; j < 8; j++)
            a[j] = *(const uint2*)&xs[(fg + j * 8) * EST + kt * 8 + 2 * fc];
#pragma unroll
        for (int nt = 0; nt < 2; nt++) {
            uint2 bv = __ldg((const uint2*)&fN2[(size_t)((w * 2 + nt) * 32 + kt) * 64 + lane * 2]);
#pragma unroll
            for (int mt = 0; mt < 4; mt++)
                MMA_TF32(o0[mt][nt], o1[mt][nt], o2[mt][nt], o3[mt][nt],
                         a[2 * mt], a[2 * mt + 1], bv);
        }
    }

#pragma unroll
    for (int mt = 0; mt < 4; mt++) {
#pragma unroll
        for (int nt = 0; nt < 2; nt++) {
            int row = row0 + mt * 16 + fg;
            int col = w * 16 + nt * 8 + 2 * fc;
            if (row < M)     *(float2*)&out[(size_t)row * 128 + col]       = make_float2(o0[mt][nt], o1[mt][nt]);
            if (row + 8 < M) *(float2*)&out[(size_t)(row + 8) * 128 + col] = make_float2(o2[mt][nt], o3[mt][nt]);
        }
    }
}

extern "C" void kernel_launch(void* const* d_in, const int* in_sizes, int n_in,
                              void* d_out, int out_size) {
    const float* nf  = (const float*)d_in[0];
    const float* ef  = (const float*)d_in[1];
    const int*   src = (const int*)d_in[2];
    const int*   dst = (const int*)d_in[3];
    const float* We1 = (const float*)d_in[4];   // (320, 256)
    const float* We2 = (const float*)d_in[5];   // (256, 128)
    const float* Wn1 = (const float*)d_in[6];   // (256, 256)
    const float* Wn2 = (const float*)d_in[7];   // (256, 128)

    const int N = in_sizes[0] / 128;
    const int E = in_sizes[2];

    float *AB, *red, *fA, *fB, *fC, *fN1, *fN2, *fE2;
    cudaGetSymbolAddress((void**)&AB, g_AB);
    cudaGetSymbolAddress((void**)&red, g_red);
    cudaGetSymbolAddress((void**)&fA, g_fA);
    cudaGetSymbolAddress((void**)&fB, g_fB);
    cudaGetSymbolAddress((void**)&fC, g_fC);
    cudaGetSymbolAddress((void**)&fN1, g_fN1);
    cudaGetSymbolAddress((void**)&fN2, g_fN2);
    cudaGetSymbolAddress((void**)&fE2, g_fE2);

    cudaFuncSetAttribute((const void*)edge_fused,
                         cudaFuncAttributeMaxDynamicSharedMemorySize, SM_EDGE);
    cudaFuncSetAttribute((const void*)node_fused,
                         cudaFuncAttributeMaxDynamicSharedMemorySize, 64 * EST * 4);

    // (0) merged one-time setup: zero red + all weight fragment shuffles
    int n4 = N * 128 / 4;
    setup_all<<<(n4 + 255) / 256, 256>>>(We1, We2, Wn1, Wn2,
                                         (float4*)red, n4, fA, fB, fC, fN1, fN2, fE2);

    // (1,2) A|B halves: nf @ We1 halves -> g_AB (row stride 512)
    mma_gemm<128, 256><<<(N + 63) / 64, 256, 64 * 136 * 4>>>(nf, fA, AB, N, 512);
    mma_gemm<128, 256><<<(N + 63) / 64, 256, 64 * 136 * 4>>>(nf, fB, AB + 256, N, 512);

    // (3) fused edge: C mma (deduped) + expand-gather + msg mma (2x4 grid) + scatter
    edge_fused<<<(E + 31) / 32, 256, SM_EDGE>>>(AB, ef, fC, fE2, src, dst, red, E);

    // (4) fused node MLP
    node_fused<<<(N + 63) / 64, 256, 64 * EST * 4>>>(nf, red, fN1, fN2, (float*)d_out, N);
}

// round 10
// speedup vs baseline: 1.8593x; 1.3529x over previous
#include <cuda_runtime.h>
#include <cstdint>

// GNN layer, all GEMMs on tf32 mma.sync m16n8k8:
//   A|B = nf @ [We1_rows0:128 | We1_rows128:256]   (per node, precomputed)
//   edge (fused): coalesced gather A[s]+B[d] -> hs (row-major);
//                 Cfrag = ef @ We1_ef (mma, M=32, once per edge);
//                 RMW: hs = rna(leaky(C + hs)) (smem, fragment pattern);
//                 msg = h @ We2 (mma, 2Mx4N warp grid); red.global.add.v4 into red[dst]
//   node (fused): hn = leaky([nf|red] @ Wn1) -> smem; out = hn @ Wn2
// Weight fragments pre-shuffled (coalesced LDG.64 B-frags):
//   Wf[((ntg*(K/8)+kt)*64 + lane*2 + j)] = rna(W[(kt*8+2*(lane&3)+j)*N + ntg*8 + (lane>>2)])

constexpr int NN_MAX = 100000;
constexpr int NE_MAX = 500000;
constexpr float NEG = 0.01f;

__device__ __align__(128) float g_AB[(size_t)NN_MAX * 512];
__device__ __align__(128) float g_red[(size_t)NN_MAX * 128];
__device__ __align__(128) float g_fA[128 * 256];
__device__ __align__(128) float g_fB[128 * 256];
__device__ __align__(128) float g_fC[64 * 256];
__device__ __align__(128) float g_fN1[256 * 256];
__device__ __align__(128) float g_fN2[256 * 128];
__device__ __align__(128) float g_fE2[256 * 128];

__device__ __forceinline__ float lky(float x) { return x >= 0.0f ? x : NEG * x; }

__device__ __forceinline__ float rna_tf32(float x) {
    float r; asm("cvt.rna.tf32.f32 %0, %1;" : "=f"(r) : "f"(x)); return r;
}

__device__ __forceinline__ void red_add_v4(float* addr, float a, float b, float c, float d) {
    asm volatile("red.global.add.v4.f32 [%0], {%1,%2,%3,%4};"
                 :: "l"(addr), "f"(a), "f"(b), "f"(c), "f"(d) : "memory");
}

#define MMA_TF32(D0, D1, D2, D3, AV, AV8, BV)                                   \
    asm volatile("mma.sync.aligned.m16n8k8.row.col.f32.tf32.tf32.f32 "          \
                 "{%0,%1,%2,%3}, {%4,%5,%6,%7}, {%8,%9}, {%0,%1,%2,%3};"        \
                 : "+f"(D0), "+f"(D1), "+f"(D2), "+f"(D3)                       \
                 : "r"((AV).x), "r"((AV8).x), "r"((AV).y), "r"((AV8).y),        \
                   "r"((BV).x), "r"((BV).y))

// ---- merged one-time setup: zero red + all weight fragment shuffles ----
template <int K, int N>
__device__ __forceinline__ void do_frag(int fi, const float* __restrict__ W,
                                        float* __restrict__ Wf) {
    if (fi >= K * N) return;
    int j = fi & 1;
    int lane = (fi >> 1) & 31;
    int kt = (fi >> 6) % (K / 8);
    int ntg = fi / (64 * (K / 8));
    int fc = lane & 3, fg = lane >> 2;
    Wf[fi] = rna_tf32(W[(kt * 8 + 2 * fc + j) * N + ntg * 8 + fg]);
}

__global__ void setup_all(const float* __restrict__ We1, const float* __restrict__ We2,
                          const float* __restrict__ Wn1, const float* __restrict__ Wn2,
                          float4* __restrict__ red4, int n4,
                          float* fA, float* fB, float* fC,
                          float* fN1, float* fN2, float* fE2) {
    int tid = blockIdx.x * 256 + threadIdx.x;
    if (tid < n4) red4[tid] = make_float4(0.f, 0.f, 0.f, 0.f);
    do_frag<128, 256>(tid, We1, fA);
    do_frag<128, 256>(tid, We1 + 128 * 256, fB);
    do_frag<64, 256>(tid, We1 + 256 * 256, fC);
    do_frag<256, 256>(tid, Wn1, fN1);
    do_frag<256, 128>(tid, Wn2, fN2);
    do_frag<256, 128>(tid, We2, fE2);
}

// ---- generic tf32 mma GEMM, 1(M)x8(N) warp grid, tile M=64 ----
template <int K, int N>
__global__ void __launch_bounds__(256, 2)
mma_gemm(const float* __restrict__ X1, const float* __restrict__ Wf,
         float* __restrict__ out, int M, int ostride) {
    constexpr int ST = K + 8;
    constexpr int KT = K / 8;
    constexpr int NT = N / 64;
    constexpr int K4 = K / 4;
    extern __shared__ float xs[];

    const int tid = threadIdx.x;
    const int row0 = blockIdx.x * 64;

    for (int idx = tid; idx < 64 * K4; idx += 256) {
        int r = idx / K4, k4 = idx % K4;
        int row = row0 + r;
        float4 v = make_float4(0.f, 0.f, 0.f, 0.f);
        if (row < M) v = ((const float4*)X1)[(size_t)row * K4 + k4];
        v.x = rna_tf32(v.x); v.y = rna_tf32(v.y);
        v.z = rna_tf32(v.z); v.w = rna_tf32(v.w);
        *(float4*)&xs[r * ST + k4 * 4] = v;
    }
    __syncthreads();

    const int w = tid >> 5, lane = tid & 31;
    const int fg = lane >> 2, fc = lane & 3;

    float d0[4][NT], d1[4][NT], d2[4][NT], d3[4][NT];
#pragma unroll
    for (int mt = 0; mt < 4; mt++)
#pragma unroll
        for (int nt = 0; nt < NT; nt++) { d0[mt][nt] = d1[mt][nt] = d2[mt][nt] = d3[mt][nt] = 0.f; }

    for (int kt = 0; kt < KT; kt++) {
        uint2 a[8];
#pragma unroll
        for (int j = 0; j < 8; j++)
            a[j] = *(const uint2*)&xs[(fg + j * 8) * ST + kt * 8 + 2 * fc];
#pragma unroll
        for (int nt = 0; nt < NT; nt++) {
            uint2 bv = __ldg((const uint2*)&Wf[(size_t)((w * NT + nt) * KT + kt) * 64 + lane * 2]);
#pragma unroll
            for (int mt = 0; mt < 4; mt++)
                MMA_TF32(d0[mt][nt], d1[mt][nt], d2[mt][nt], d3[mt][nt],
                         a[2 * mt], a[2 * mt + 1], bv);
        }
    }

#pragma unroll
    for (int mt = 0; mt < 4; mt++) {
#pragma unroll
        for (int nt = 0; nt < NT; nt++) {
            int row = row0 + mt * 16 + fg;
            int col = w * (NT * 8) + nt * 8 + 2 * fc;
            if (row < M)     *(float2*)&out[(size_t)row * ostride + col]       = make_float2(d0[mt][nt], d1[mt][nt]);
            if (row + 8 < M) *(float2*)&out[(size_t)(row + 8) * ostride + col] = make_float2(d2[mt][nt], d3[mt][nt]);
        }
    }
}

// ---- fused edge kernel: tile = 32 edges -> 64 edge-dir rows ----
constexpr int EST = 264;
constexpr int SM_EDGE = 64 * EST * 4;   // 67584 B

__global__ void __launch_bounds__(256, 3)
edge_fused(const float* __restrict__ AB, const float* __restrict__ ef,
           const float* __restrict__ fC, const float* __restrict__ fE2,
           const int* __restrict__ src, const int* __restrict__ dst,
           float* __restrict__ red, int E) {
    extern __shared__ float hs[];   // 64 * 264 row-major
    __shared__ int ss[64], dds[64];

    const int tid = threadIdx.x;
    const int t = blockIdx.x;

    if (tid < 64) {
        int er = tid >> 1;
        bool rev = tid & 1;
        int e = t * 32 + er;
        int sv = -1, dv = -1;
        if (e < E) { sv = src[e]; dv = dst[e]; }
        ss[tid]  = rev ? dv : sv;
        dds[tid] = rev ? sv : dv;
    }
    __syncthreads();

    const int w = tid >> 5, lane = tid & 31;
    const int fg = lane >> 2, fc = lane & 3;

    // ---- phase 1a: coalesced gather A[s]+B[d] -> hs (warp w owns rows w*8..w*8+7) ----
#pragma unroll
    for (int i = 0; i < 8; i++) {
        const int hr = w * 8 + i;
        const int s = ss[hr], d = dds[hr];
        float4 h0 = make_float4(0.f, 0.f, 0.f, 0.f);
        float4 h1 = h0;
        if (s >= 0) {
            const float4* pa = (const float4*)(AB + (size_t)s * 512);
            const float4* pb = (const float4*)(AB + (size_t)d * 512 + 256);
            float4 a0 = pa[lane], a1 = pa[32 + lane];
            float4 b0 = pb[lane], b1 = pb[32 + lane];
            h0 = make_float4(a0.x + b0.x, a0.y + b0.y, a0.z + b0.z, a0.w + b0.w);
            h1 = make_float4(a1.x + b1.x, a1.y + b1.y, a1.z + b1.z, a1.w + b1.w);
        }
        *(float4*)&hs[hr * EST + lane * 4] = h0;
        *(float4*)&hs[hr * EST + 128 + lane * 4] = h1;
    }
    __syncthreads();

    // ef element offsets for this thread's 4 fragment edge-rows (M=32 C tile)
    int eo[4];
#pragma unroll
    for (int j = 0; j < 4; j++) {
        int e = t * 32 + fg + j * 8;
        if (e >= E) e = 0;
        eo[j] = e * 64;
    }

    // ---- phase 1b: C mma (M=32, K=64) once per edge; RMW hs frags (smem) ----
#pragma unroll
    for (int ch = 0; ch < 2; ch++) {           // per-warp NT=4, chunks of 2
        float d0[2][2], d1[2][2], d2[2][2], d3[2][2];
#pragma unroll
        for (int mt = 0; mt < 2; mt++)
#pragma unroll
            for (int nt = 0; nt < 2; nt++) { d0[mt][nt] = d1[mt][nt] = d2[mt][nt] = d3[mt][nt] = 0.f; }

#pragma unroll
        for (int kt = 0; kt < 8; kt++) {
            uint2 a[4];
#pragma unroll
            for (int j = 0; j < 4; j++)
                a[j] = __ldg((const uint2*)&ef[eo[j] + kt * 8 + 2 * fc]);
#pragma unroll
            for (int nt = 0; nt < 2; nt++) {
                int ntg = w * 4 + ch * 2 + nt;
                uint2 bv = __ldg((const uint2*)&fC[(size_t)(ntg * 8 + kt) * 64 + lane * 2]);
#pragma unroll
                for (int mt = 0; mt < 2; mt++)
                    MMA_TF32(d0[mt][nt], d1[mt][nt], d2[mt][nt], d3[mt][nt],
                             a[2 * mt], a[2 * mt + 1], bv);
            }
        }

        // RMW: hs = rna(leaky(C + hs)) for both dir rows of each edge row
#pragma unroll
        for (int mt = 0; mt < 2; mt++) {
#pragma unroll
            for (int nt = 0; nt < 2; nt++) {
                int col = w * 32 + (ch * 2 + nt) * 8 + 2 * fc;
#pragma unroll
                for (int half = 0; half < 2; half++) {
                    int er = mt * 16 + fg + half * 8;          // edge row 0..31
                    float cx = half ? d2[mt][nt] : d0[mt][nt];
                    float cy = half ? d3[mt][nt] : d1[mt][nt];
#pragma unroll
                    for (int dir = 0; dir < 2; dir++) {
                        int hr = 2 * er + dir;
                        float2 hv = *(float2*)&hs[hr * EST + col];
                        hv.x = rna_tf32(lky(cx + hv.x));
                        hv.y = rna_tf32(lky(cy + hv.y));
                        *(float2*)&hs[hr * EST + col] = hv;
                    }
                }
            }
        }
    }
    __syncthreads();

    // ---- phase 2: msg = h @ We2; 2(M) x 4(N) warp grid, Mw=32, Nw=32 ----
    const int wm = w & 1, wc = w >> 1;
    const int rb = wm * 32;

    float e0[2][4], e1[2][4], e2[2][4], e3[2][4];
#pragma unroll
    for (int mt = 0; mt < 2; mt++)
#pragma unroll
        for (int nt = 0; nt < 4; nt++) { e0[mt][nt] = e1[mt][nt] = e2[mt][nt] = e3[mt][nt] = 0.f; }

    for (int kt = 0; kt < 32; kt++) {
        uint2 a[4];
#pragma unroll
        for (int j = 0; j < 4; j++)
            a[j] = *(const uint2*)&hs[(rb + fg + j * 8) * EST + kt * 8 + 2 * fc];
#pragma unroll
        for (int nt = 0; nt < 4; nt++) {
            uint2 bv = __ldg((const uint2*)&fE2[(size_t)((wc * 4 + nt) * 32 + kt) * 64 + lane * 2]);
#pragma unroll
            for (int mt = 0; mt < 2; mt++)
                MMA_TF32(e0[mt][nt], e1[mt][nt], e2[mt][nt], e3[mt][nt],
                         a[2 * mt], a[2 * mt + 1], bv);
        }
    }

    // ---- scatter-add (v4 via lane pairing) ----
#pragma unroll
    for (int mt = 0; mt < 2; mt++) {
        int rowA = rb + mt * 16 + fg;
        int dA = dds[rowA];
        int dB = dds[rowA + 8];
#pragma unroll
        for (int nt = 0; nt < 4; nt++) {
            float s0 = __shfl_down_sync(0xffffffffu, e0[mt][nt], 1);
            float s1 = __shfl_down_sync(0xffffffffu, e1[mt][nt], 1);
            float s2 = __shfl_down_sync(0xffffffffu, e2[mt][nt], 1);
            float s3 = __shfl_down_sync(0xffffffffu, e3[mt][nt], 1);
            if ((fc & 1) == 0) {
                int col = wc * 32 + nt * 8 + 2 * fc;
                if (dA >= 0) red_add_v4(&red[(size_t)dA * 128 + col], e0[mt][nt], e1[mt][nt], s0, s1);
                if (dB >= 0) red_add_v4(&red[(size_t)dB * 128 + col], e2[mt][nt], e3[mt][nt], s2, s3);
            }
        }
    }
}

// ---- fused node MLP: hn = leaky([nf|red] @ Wn1); out = hn @ Wn2 ----
__global__ void __launch_bounds__(256, 2)
node_fused(const float* __restrict__ nf, const float* __restrict__ red,
           const float* __restrict__ fN1, const float* __restrict__ fN2,
           float* __restrict__ out, int M) {
    extern __shared__ float xs[];   // 64 * 264
    const int tid = threadIdx.x;
    const int row0 = blockIdx.x * 64;

    for (int idx = tid; idx < 64 * 64; idx += 256) {
        int r = idx >> 6, k4 = idx & 63;
        int row = row0 + r;
        float4 v = make_float4(0.f, 0.f, 0.f, 0.f);
        if (row < M)
            v = (k4 < 32) ? ((const float4*)nf)[(size_t)row * 32 + k4]
                          : ((const float4*)red)[(size_t)row * 32 + (k4 - 32)];
        v.x = rna_tf32(v.x); v.y = rna_tf32(v.y);
        v.z = rna_tf32(v.z); v.w = rna_tf32(v.w);
        *(float4*)&xs[r * EST + k4 * 4] = v;
    }
    __syncthreads();

    const int w = tid >> 5, lane = tid & 31;
    const int fg = lane >> 2, fc = lane & 3;

    float h0[4][4], h1[4][4], h2[4][4], h3[4][4];
#pragma unroll
    for (int mt = 0; mt < 4; mt++)
#pragma unroll
        for (int nt = 0; nt < 4; nt++) { h0[mt][nt] = h1[mt][nt] = h2[mt][nt] = h3[mt][nt] = 0.f; }

    for (int kt = 0; kt < 32; kt++) {
        uint2 a[8];
#pragma unroll
        for (int j = 0; j < 8; j++)
            a[j] = *(const uint2*)&xs[(fg + j * 8) * EST + kt * 8 + 2 * fc];
#pragma unroll
        for (int nt = 0; nt < 4; nt++) {
            uint2 bv = __ldg((const uint2*)&fN1[(size_t)((w * 4 + nt) * 32 + kt) * 64 + lane * 2]);
#pragma unroll
            for (int mt = 0; mt < 4; mt++)
                MMA_TF32(h0[mt][nt], h1[mt][nt], h2[mt][nt], h3[mt][nt],
                         a[2 * mt], a[2 * mt + 1], bv);
        }
    }
    __syncthreads();

#pragma unroll
    for (int mt = 0; mt < 4; mt++) {
#pragma unroll
        for (int nt = 0; nt < 4; nt++) {
            int row = mt * 16 + fg;
            int col = w * 32 + nt * 8 + 2 * fc;
            *(float2*)&xs[row * EST + col] =
                make_float2(rna_tf32(lky(h0[mt][nt])), rna_tf32(lky(h1[mt][nt])));
            *(float2*)&xs[(row + 8) * EST + col] =
                make_float2(rna_tf32(lky(h2[mt][nt])), rna_tf32(lky(h3[mt][nt])));
        }
    }
    __syncthreads();

    float o0[4][2], o1[4][2], o2[4][2], o3[4][2];
#pragma unroll
    for (int mt = 0; mt < 4; mt++)
#pragma unroll
        for (int nt = 0; nt < 2; nt++) { o0[mt][nt] = o1[mt][nt] = o2[mt][nt] = o3[mt][nt] = 0.f; }

    for (int kt = 0; kt < 32; kt++) {
        uint2 a[8];
#pragma unroll
        for (int j = 0; j < 8; j++)
            a[j] = *(const uint2*)&xs[(fg + j * 8) * EST + kt * 8 + 2 * fc];
#pragma unroll
        for (int nt = 0; nt < 2; nt++) {
            uint2 bv = __ldg((const uint2*)&fN2[(size_t)((w * 2 + nt) * 32 + kt) * 64 + lane * 2]);
#pragma unroll
            for (int mt = 0; mt < 4; mt++)
                MMA_TF32(o0[mt][nt], o1[mt][nt], o2[mt][nt], o3[mt][nt],
                         a[2 * mt], a[2 * mt + 1], bv);
        }
    }

#pragma unroll
    for (int mt = 0; mt < 4; mt++) {
#pragma unroll
        for (int nt = 0; nt < 2; nt++) {
            int row = row0 + mt * 16 + fg;
            int col = w * 16 + nt * 8 + 2 * fc;
            if (row < M)     *(float2*)&out[(size_t)row * 128 + col]       = make_float2(o0[mt][nt], o1[mt][nt]);
            if (row + 8 < M) *(float2*)&out[(size_t)(row + 8) * 128 + col] = make_float2(o2[mt][nt], o3[mt][nt]);
        }
    }
}

extern "C" void kernel_launch(void* const* d_in, const int* in_sizes, int n_in,
                              void* d_out, int out_size) {
    const float* nf  = (const float*)d_in[0];
    const float* ef  = (const float*)d_in[1];
    const int*   src = (const int*)d_in[2];
    const int*   dst = (const int*)d_in[3];
    const float* We1 = (const float*)d_in[4];   // (320, 256)
    const float* We2 = (const float*)d_in[5];   // (256, 128)
    const float* Wn1 = (const float*)d_in[6];   // (256, 256)
    const float* Wn2 = (const float*)d_in[7];   // (256, 128)

    const int N = in_sizes[0] / 128;
    const int E = in_sizes[2];

    float *AB, *red, *fA, *fB, *fC, *fN1, *fN2, *fE2;
    cudaGetSymbolAddress((void**)&AB, g_AB);
    cudaGetSymbolAddress((void**)&red, g_red);
    cudaGetSymbolAddress((void**)&fA, g_fA);
    cudaGetSymbolAddress((void**)&fB, g_fB);
    cudaGetSymbolAddress((void**)&fC, g_fC);
    cudaGetSymbolAddress((void**)&fN1, g_fN1);
    cudaGetSymbolAddress((void**)&fN2, g_fN2);
    cudaGetSymbolAddress((void**)&fE2, g_fE2);

    cudaFuncSetAttribute((const void*)edge_fused,
                         cudaFuncAttributeMaxDynamicSharedMemorySize, SM_EDGE);
    cudaFuncSetAttribute((const void*)node_fused,
                         cudaFuncAttributeMaxDynamicSharedMemorySize, 64 * EST * 4);

    // (0) merged one-time setup: zero red + all weight fragment shuffles
    int n4 = N * 128 / 4;
    setup_all<<<(n4 + 255) / 256, 256>>>(We1, We2, Wn1, Wn2,
                                         (float4*)red, n4, fA, fB, fC, fN1, fN2, fE2);

    // (1,2) A|B halves: nf @ We1 halves -> g_AB (row stride 512)
    mma_gemm<128, 256><<<(N + 63) / 64, 256, 64 * 136 * 4>>>(nf, fA, AB, N, 512);
    mma_gemm<128, 256><<<(N + 63) / 64, 256, 64 * 136 * 4>>>(nf, fB, AB + 256, N, 512);

    // (3) fused edge: coalesced gather + C mma + RMW + msg mma + scatter
    edge_fused<<<(E + 31) / 32, 256, SM_EDGE>>>(AB, ef, fC, fE2, src, dst, red, E);

    // (4) fused node MLP
    node_fused<<<(N + 63) / 64, 256, 64 * EST * 4>>>(nf, red, fN1, fN2, (float*)d_out, N);
}

// round 11
// speedup vs baseline: 1.9372x; 1.0419x over previous
#include <cuda_runtime.h>
#include <cstdint>

// GNN layer, all GEMMs on tf32 mma.sync m16n8k8:
//   A|B = nf @ [We1_rows0:128 | We1_rows128:256]   (per node, precomputed)
//   edge (fused): coalesced gather A[s]+B[d] -> hs; ef tile staged -> smem (coalesced);
//                 Cfrag = ef @ We1_ef (mma, M=32, once per edge, A-frags from smem);
//                 RMW: hs = rna(leaky(C + hs)) (smem);
//                 msg = h @ We2 (mma, 2Mx4N warp grid); red.global.add.v4 into red[dst]
//   node (fused): hn = leaky([nf|red] @ Wn1) -> smem; out = hn @ Wn2
// Weight fragments pre-shuffled (coalesced LDG.64 B-frags):
//   Wf[((ntg*(K/8)+kt)*64 + lane*2 + j)] = rna(W[(kt*8+2*(lane&3)+j)*N + ntg*8 + (lane>>2)])

constexpr int NN_MAX = 100000;
constexpr int NE_MAX = 500000;
constexpr float NEG = 0.01f;

__device__ __align__(128) float g_AB[(size_t)NN_MAX * 512];
__device__ __align__(128) float g_red[(size_t)NN_MAX * 128];
__device__ __align__(128) float g_fA[128 * 256];
__device__ __align__(128) float g_fB[128 * 256];
__device__ __align__(128) float g_fC[64 * 256];
__device__ __align__(128) float g_fN1[256 * 256];
__device__ __align__(128) float g_fN2[256 * 128];
__device__ __align__(128) float g_fE2[256 * 128];

__device__ __forceinline__ float lky(float x) { return x >= 0.0f ? x : NEG * x; }

__device__ __forceinline__ float rna_tf32(float x) {
    float r; asm("cvt.rna.tf32.f32 %0, %1;" : "=f"(r) : "f"(x)); return r;
}

__device__ __forceinline__ void red_add_v4(float* addr, float a, float b, float c, float d) {
    asm volatile("red.global.add.v4.f32 [%0], {%1,%2,%3,%4};"
                 :: "l"(addr), "f"(a), "f"(b), "f"(c), "f"(d) : "memory");
}

#define MMA_TF32(D0, D1, D2, D3, AV, AV8, BV)                                   \
    asm volatile("mma.sync.aligned.m16n8k8.row.col.f32.tf32.tf32.f32 "          \
                 "{%0,%1,%2,%3}, {%4,%5,%6,%7}, {%8,%9}, {%0,%1,%2,%3};"        \
                 : "+f"(D0), "+f"(D1), "+f"(D2), "+f"(D3)                       \
                 : "r"((AV).x), "r"((AV8).x), "r"((AV).y), "r"((AV8).y),        \
                   "r"((BV).x), "r"((BV).y))

// ---- merged one-time setup: zero red + all weight fragment shuffles ----
template <int K, int N>
__device__ __forceinline__ void do_frag(int fi, const float* __restrict__ W,
                                        float* __restrict__ Wf) {
    if (fi >= K * N) return;
    int j = fi & 1;
    int lane = (fi >> 1) & 31;
    int kt = (fi >> 6) % (K / 8);
    int ntg = fi / (64 * (K / 8));
    int fc = lane & 3, fg = lane >> 2;
    Wf[fi] = rna_tf32(W[(kt * 8 + 2 * fc + j) * N + ntg * 8 + fg]);
}

__global__ void setup_all(const float* __restrict__ We1, const float* __restrict__ We2,
                          const float* __restrict__ Wn1, const float* __restrict__ Wn2,
                          float4* __restrict__ red4, int n4,
                          float* fA, float* fB, float* fC,
                          float* fN1, float* fN2, float* fE2) {
    int tid = blockIdx.x * 256 + threadIdx.x;
    if (tid < n4) red4[tid] = make_float4(0.f, 0.f, 0.f, 0.f);
    do_frag<128, 256>(tid, We1, fA);
    do_frag<128, 256>(tid, We1 + 128 * 256, fB);
    do_frag<64, 256>(tid, We1 + 256 * 256, fC);
    do_frag<256, 256>(tid, Wn1, fN1);
    do_frag<256, 128>(tid, Wn2, fN2);
    do_frag<256, 128>(tid, We2, fE2);
}

// ---- generic tf32 mma GEMM, 1(M)x8(N) warp grid, tile M=64 ----
template <int K, int N>
__global__ void __launch_bounds__(256, 2)
mma_gemm(const float* __restrict__ X1, const float* __restrict__ Wf,
         float* __restrict__ out, int M, int ostride) {
    constexpr int ST = K + 8;
    constexpr int KT = K / 8;
    constexpr int NT = N / 64;
    constexpr int K4 = K / 4;
    extern __shared__ float xs[];

    const int tid = threadIdx.x;
    const int row0 = blockIdx.x * 64;

    for (int idx = tid; idx < 64 * K4; idx += 256) {
        int r = idx / K4, k4 = idx % K4;
        int row = row0 + r;
        float4 v = make_float4(0.f, 0.f, 0.f, 0.f);
        if (row < M) v = ((const float4*)X1)[(size_t)row * K4 + k4];
        v.x = rna_tf32(v.x); v.y = rna_tf32(v.y);
        v.z = rna_tf32(v.z); v.w = rna_tf32(v.w);
        *(float4*)&xs[r * ST + k4 * 4] = v;
    }
    __syncthreads();

    const int w = tid >> 5, lane = tid & 31;
    const int fg = lane >> 2, fc = lane & 3;

    float d0[4][NT], d1[4][NT], d2[4][NT], d3[4][NT];
#pragma unroll
    for (int mt = 0; mt < 4; mt++)
#pragma unroll
        for (int nt = 0; nt < NT; nt++) { d0[mt][nt] = d1[mt][nt] = d2[mt][nt] = d3[mt][nt] = 0.f; }

    for (int kt = 0; kt < KT; kt++) {
        uint2 a[8];
#pragma unroll
        for (int j = 0; j < 8; j++)
            a[j] = *(const uint2*)&xs[(fg + j * 8) * ST + kt * 8 + 2 * fc];
#pragma unroll
        for (int nt = 0; nt < NT; nt++) {
            uint2 bv = __ldg((const uint2*)&Wf[(size_t)((w * NT + nt) * KT + kt) * 64 + lane * 2]);
#pragma unroll
            for (int mt = 0; mt < 4; mt++)
                MMA_TF32(d0[mt][nt], d1[mt][nt], d2[mt][nt], d3[mt][nt],
                         a[2 * mt], a[2 * mt + 1], bv);
        }
    }

#pragma unroll
    for (int mt = 0; mt < 4; mt++) {
#pragma unroll
        for (int nt = 0; nt < NT; nt++) {
            int row = row0 + mt * 16 + fg;
            int col = w * (NT * 8) + nt * 8 + 2 * fc;
            if (row < M)     *(float2*)&out[(size_t)row * ostride + col]       = make_float2(d0[mt][nt], d1[mt][nt]);
            if (row + 8 < M) *(float2*)&out[(size_t)(row + 8) * ostride + col] = make_float2(d2[mt][nt], d3[mt][nt]);
        }
    }
}

// ---- fused edge kernel: tile = 32 edges -> 64 edge-dir rows ----
constexpr int EST = 264;
constexpr int EFST = 68;                               // padded ef smem row stride
constexpr int EFS_OFF = 64 * EST;                      // float offset of ef tile in smem
constexpr int SM_EDGE = (64 * EST + 32 * EFST) * 4;    // 76288 B

__global__ void __launch_bounds__(256, 3)
edge_fused(const float* __restrict__ AB, const float* __restrict__ ef,
           const float* __restrict__ fC, const float* __restrict__ fE2,
           const int* __restrict__ src, const int* __restrict__ dst,
           float* __restrict__ red, int E) {
    extern __shared__ float hs[];   // [0,64*264): h rows; [EFS_OFF, +32*68): ef tile
    float* efs = hs + EFS_OFF;
    __shared__ int ss[64], dds[64];

    const int tid = threadIdx.x;
    const int t = blockIdx.x;

    if (tid < 64) {
        int er = tid >> 1;
        bool rev = tid & 1;
        int e = t * 32 + er;
        int sv = -1, dv = -1;
        if (e < E) { sv = src[e]; dv = dst[e]; }
        ss[tid]  = rev ? dv : sv;
        dds[tid] = rev ? sv : dv;
    }
    __syncthreads();

    const int w = tid >> 5, lane = tid & 31;
    const int fg = lane >> 2, fc = lane & 3;

    // ---- phase 1a-i: stage ef tile (contiguous 8 KB) -> smem, coalesced ----
    {
        const int maxe = E - t * 32;            // edges in this tile (may exceed 32)
        const float4* eft = (const float4*)(ef + (size_t)t * 32 * 64);
#pragma unroll
        for (int it = 0; it < 2; it++) {
            int idx = tid + it * 256;           // 0..511 = 32 rows x 16 float4
            int r = idx >> 4, c4 = idx & 15;
            float4 v = make_float4(0.f, 0.f, 0.f, 0.f);
            if (r < maxe) v = eft[idx];
            *(float4*)&efs[r * EFST + c4 * 4] = v;
        }
    }

    // ---- phase 1a-ii: coalesced gather A[s]+B[d] -> hs (warp w owns rows w*8..w*8+7) ----
#pragma unroll
    for (int i = 0; i < 8; i++) {
        const int hr = w * 8 + i;
        const int s = ss[hr], d = dds[hr];
        float4 h0 = make_float4(0.f, 0.f, 0.f, 0.f);
        float4 h1 = h0;
        if (s >= 0) {
            const float4* pa = (const float4*)(AB + (size_t)s * 512);
            const float4* pb = (const float4*)(AB + (size_t)d * 512 + 256);
            float4 a0 = pa[lane], a1 = pa[32 + lane];
            float4 b0 = pb[lane], b1 = pb[32 + lane];
            h0 = make_float4(a0.x + b0.x, a0.y + b0.y, a0.z + b0.z, a0.w + b0.w);
            h1 = make_float4(a1.x + b1.x, a1.y + b1.y, a1.z + b1.z, a1.w + b1.w);
        }
        *(float4*)&hs[hr * EST + lane * 4] = h0;
        *(float4*)&hs[hr * EST + 128 + lane * 4] = h1;
    }
    __syncthreads();

    // ---- phase 1b: C mma (M=32, K=64) once per edge; RMW hs frags (smem) ----
#pragma unroll
    for (int ch = 0; ch < 2; ch++) {           // per-warp NT=4, chunks of 2
        float d0[2][2], d1[2][2], d2[2][2], d3[2][2];
#pragma unroll
        for (int mt = 0; mt < 2; mt++)
#pragma unroll
            for (int nt = 0; nt < 2; nt++) { d0[mt][nt] = d1[mt][nt] = d2[mt][nt] = d3[mt][nt] = 0.f; }

#pragma unroll
        for (int kt = 0; kt < 8; kt++) {
            uint2 a[4];
#pragma unroll
            for (int j = 0; j < 4; j++)
                a[j] = *(const uint2*)&efs[(fg + j * 8) * EFST + kt * 8 + 2 * fc];
#pragma unroll
            for (int nt = 0; nt < 2; nt++) {
                int ntg = w * 4 + ch * 2 + nt;
                uint2 bv = __ldg((const uint2*)&fC[(size_t)(ntg * 8 + kt) * 64 + lane * 2]);
#pragma unroll
                for (int mt = 0; mt < 2; mt++)
                    MMA_TF32(d0[mt][nt], d1[mt][nt], d2[mt][nt], d3[mt][nt],
                             a[2 * mt], a[2 * mt + 1], bv);
            }
        }

        // RMW: hs = rna(leaky(C + hs)) for both dir rows of each edge row
#pragma unroll
        for (int mt = 0; mt < 2; mt++) {
#pragma unroll
            for (int nt = 0; nt < 2; nt++) {
                int col = w * 32 + (ch * 2 + nt) * 8 + 2 * fc;
#pragma unroll
                for (int half = 0; half < 2; half++) {
                    int er = mt * 16 + fg + half * 8;          // edge row 0..31
                    float cx = half ? d2[mt][nt] : d0[mt][nt];
                    float cy = half ? d3[mt][nt] : d1[mt][nt];
#pragma unroll
                    for (int dir = 0; dir < 2; dir++) {
                        int hr = 2 * er + dir;
                        float2 hv = *(float2*)&hs[hr * EST + col];
                        hv.x = rna_tf32(lky(cx + hv.x));
                        hv.y = rna_tf32(lky(cy + hv.y));
                        *(float2*)&hs[hr * EST + col] = hv;
                    }
                }
            }
        }
    }
    __syncthreads();

    // ---- phase 2: msg = h @ We2; 2(M) x 4(N) warp grid, Mw=32, Nw=32 ----
    const int wm = w & 1, wc = w >> 1;
    const int rb = wm * 32;

    float e0[2][4], e1[2][4], e2[2][4], e3[2][4];
#pragma unroll
    for (int mt = 0; mt < 2; mt++)
#pragma unroll
        for (int nt = 0; nt < 4; nt++) { e0[mt][nt] = e1[mt][nt] = e2[mt][nt] = e3[mt][nt] = 0.f; }

    for (int kt = 0; kt < 32; kt++) {
        uint2 a[4];
#pragma unroll
        for (int j = 0; j < 4; j++)
            a[j] = *(const uint2*)&hs[(rb + fg + j * 8) * EST + kt * 8 + 2 * fc];
#pragma unroll
        for (int nt = 0; nt < 4; nt++) {
            uint2 bv = __ldg((const uint2*)&fE2[(size_t)((wc * 4 + nt) * 32 + kt) * 64 + lane * 2]);
#pragma unroll
            for (int mt = 0; mt < 2; mt++)
                MMA_TF32(e0[mt][nt], e1[mt][nt], e2[mt][nt], e3[mt][nt],
                         a[2 * mt], a[2 * mt + 1], bv);
        }
    }

    // ---- scatter-add (v4 via lane pairing) ----
#pragma unroll
    for (int mt = 0; mt < 2; mt++) {
        int rowA = rb + mt * 16 + fg;
        int dA = dds[rowA];
        int dB = dds[rowA + 8];
#pragma unroll
        for (int nt = 0; nt < 4; nt++) {
            float s0 = __shfl_down_sync(0xffffffffu, e0[mt][nt], 1);
            float s1 = __shfl_down_sync(0xffffffffu, e1[mt][nt], 1);
            float s2 = __shfl_down_sync(0xffffffffu, e2[mt][nt], 1);
            float s3 = __shfl_down_sync(0xffffffffu, e3[mt][nt], 1);
            if ((fc & 1) == 0) {
                int col = wc * 32 + nt * 8 + 2 * fc;
                if (dA >= 0) red_add_v4(&red[(size_t)dA * 128 + col], e0[mt][nt], e1[mt][nt], s0, s1);
                if (dB >= 0) red_add_v4(&red[(size_t)dB * 128 + col], e2[mt][nt], e3[mt][nt], s2, s3);
            }
        }
    }
}

// ---- fused node MLP: hn = leaky([nf|red] @ Wn1); out = hn @ Wn2 ----
__global__ void __launch_bounds__(256, 2)
node_fused(const float* __restrict__ nf, const float* __restrict__ red,
           const float* __restrict__ fN1, const float* __restrict__ fN2,
           float* __restrict__ out, int M) {
    extern __shared__ float xs[];   // 64 * 264
    const int tid = threadIdx.x;
    const int row0 = blockIdx.x * 64;

    for (int idx = tid; idx < 64 * 64; idx += 256) {
        int r = idx >> 6, k4 = idx & 63;
        int row = row0 + r;
        float4 v = make_float4(0.f, 0.f, 0.f, 0.f);
        if (row < M)
            v = (k4 < 32) ? ((const float4*)nf)[(size_t)row * 32 + k4]
                          : ((const float4*)red)[(size_t)row * 32 + (k4 - 32)];
        v.x = rna_tf32(v.x); v.y = rna_tf32(v.y);
        v.z = rna_tf32(v.z); v.w = rna_tf32(v.w);
        *(float4*)&xs[r * EST + k4 * 4] = v;
    }
    __syncthreads();

    const int w = tid >> 5, lane = tid & 31;
    const int fg = lane >> 2, fc = lane & 3;

    float h0[4][4], h1[4][4], h2[4][4], h3[4][4];
#pragma unroll
    for (int mt = 0; mt < 4; mt++)
#pragma unroll
        for (int nt = 0; nt < 4; nt++) { h0[mt][nt] = h1[mt][nt] = h2[mt][nt] = h3[mt][nt] = 0.f; }

    for (int kt = 0; kt < 32; kt++) {
        uint2 a[8];
#pragma unroll
        for (int j = 0; j < 8; j++)
            a[j] = *(const uint2*)&xs[(fg + j * 8) * EST + kt * 8 + 2 * fc];
#pragma unroll
        for (int nt = 0; nt < 4; nt++) {
            uint2 bv = __ldg((const uint2*)&fN1[(size_t)((w * 4 + nt) * 32 + kt) * 64 + lane * 2]);
#pragma unroll
            for (int mt = 0; mt < 4; mt++)
                MMA_TF32(h0[mt][nt], h1[mt][nt], h2[mt][nt], h3[mt][nt],
                         a[2 * mt], a[2 * mt + 1], bv);
        }
    }
    __syncthreads();

#pragma unroll
    for (int mt = 0; mt < 4; mt++) {
#pragma unroll
        for (int nt = 0; nt < 4; nt++) {
            int row = mt * 16 + fg;
            int col = w * 32 + nt * 8 + 2 * fc;
            *(float2*)&xs[row * EST + col] =
                make_float2(rna_tf32(lky(h0[mt][nt])), rna_tf32(lky(h1[mt][nt])));
            *(float2*)&xs[(row + 8) * EST + col] =
                make_float2(rna_tf32(lky(h2[mt][nt])), rna_tf32(lky(h3[mt][nt])));
        }
    }
    __syncthreads();

    float o0[4][2], o1[4][2], o2[4][2], o3[4][2];
#pragma unroll
    for (int mt = 0; mt < 4; mt++)
#pragma unroll
        for (int nt = 0; nt < 2; nt++) { o0[mt][nt] = o1[mt][nt] = o2[mt][nt] = o3[mt][nt] = 0.f; }

    for (int kt = 0; kt < 32; kt++) {
        uint2 a[8];
#pragma unroll
        for (int j = 0; j < 8; j++)
            a[j] = *(const uint2*)&xs[(fg + j * 8) * EST + kt * 8 + 2 * fc];
#pragma unroll
        for (int nt = 0; nt < 2; nt++) {
            uint2 bv = __ldg((const uint2*)&fN2[(size_t)((w * 2 + nt) * 32 + kt) * 64 + lane * 2]);
#pragma unroll
            for (int mt = 0; mt < 4; mt++)
                MMA_TF32(o0[mt][nt], o1[mt][nt], o2[mt][nt], o3[mt][nt],
                         a[2 * mt], a[2 * mt + 1], bv);
        }
    }

#pragma unroll
    for (int mt = 0; mt < 4; mt++) {
#pragma unroll
        for (int nt = 0; nt < 2; nt++) {
            int row = row0 + mt * 16 + fg;
            int col = w * 16 + nt * 8 + 2 * fc;
            if (row < M)     *(float2*)&out[(size_t)row * 128 + col]       = make_float2(o0[mt][nt], o1[mt][nt]);
            if (row + 8 < M) *(float2*)&out[(size_t)(row + 8) * 128 + col] = make_float2(o2[mt][nt], o3[mt][nt]);
        }
    }
}

extern "C" void kernel_launch(void* const* d_in, const int* in_sizes, int n_in,
                              void* d_out, int out_size) {
    const float* nf  = (const float*)d_in[0];
    const float* ef  = (const float*)d_in[1];
    const int*   src = (const int*)d_in[2];
    const int*   dst = (const int*)d_in[3];
    const float* We1 = (const float*)d_in[4];   // (320, 256)
    const float* We2 = (const float*)d_in[5];   // (256, 128)
    const float* Wn1 = (const float*)d_in[6];   // (256, 256)
    const float* Wn2 = (const float*)d_in[7];   // (256, 128)

    const int N = in_sizes[0] / 128;
    const int E = in_sizes[2];

    float *AB, *red, *fA, *fB, *fC, *fN1, *fN2, *fE2;
    cudaGetSymbolAddress((void**)&AB, g_AB);
    cudaGetSymbolAddress((void**)&red, g_red);
    cudaGetSymbolAddress((void**)&fA, g_fA);
    cudaGetSymbolAddress((void**)&fB, g_fB);
    cudaGetSymbolAddress((void**)&fC, g_fC);
    cudaGetSymbolAddress((void**)&fN1, g_fN1);
    cudaGetSymbolAddress((void**)&fN2, g_fN2);
    cudaGetSymbolAddress((void**)&fE2, g_fE2);

    cudaFuncSetAttribute((const void*)edge_fused,
                         cudaFuncAttributeMaxDynamicSharedMemorySize, SM_EDGE);
    cudaFuncSetAttribute((const void*)node_fused,
                         cudaFuncAttributeMaxDynamicSharedMemorySize, 64 * EST * 4);

    // (0) merged one-time setup: zero red + all weight fragment shuffles
    int n4 = N * 128 / 4;
    setup_all<<<(n4 + 255) / 256, 256>>>(We1, We2, Wn1, Wn2,
                                         (float4*)red, n4, fA, fB, fC, fN1, fN2, fE2);

    // (1,2) A|B halves: nf @ We1 halves -> g_AB (row stride 512)
    mma_gemm<128, 256><<<(N + 63) / 64, 256, 64 * 136 * 4>>>(nf, fA, AB, N, 512);
    mma_gemm<128, 256><<<(N + 63) / 64, 256, 64 * 136 * 4>>>(nf, fB, AB + 256, N, 512);

    // (3) fused edge: staged ef + coalesced gather + C mma + RMW + msg mma + scatter
    edge_fused<<<(E + 31) / 32, 256, SM_EDGE>>>(AB, ef, fC, fE2, src, dst, red, E);

    // (4) fused node MLP
    node_fused<<<(N + 63) / 64, 256, 64 * EST * 4>>>(nf, red, fN1, fN2, (float*)d_out, N);
}

// round 12
// speedup vs baseline: 2.0215x; 1.0435x over previous
#include <cuda_runtime.h>
#include <cstdint>

// GNN layer, all GEMMs on tf32 mma.sync m16n8k8:
//   A|B = nf @ We1 halves (per node, one fused kernel)
//   edge (fused): ef tile staged -> smem; Cfrag = ef @ We1_ef (mma, M=32, once/edge),
//                 D-frags stored RAW into even hs rows;
//                 pair-fused gather: h_fwd/h_rev = rna(leaky(C + A/B combos)) -> hs;
//                 msg = h @ We2 (mma, 2Mx4N); red.global.add.v4 into red[dst]
//   node (fused): hn = leaky([nf|red] @ Wn1) -> smem; out = hn @ Wn2
// Weight fragments pre-shuffled (coalesced LDG.64 B-frags):
//   Wf[((ntg*(K/8)+kt)*64 + lane*2 + j)] = rna(W[(kt*8+2*(lane&3)+j)*N + ntg*8 + (lane>>2)])

constexpr int NN_MAX = 100000;
constexpr int NE_MAX = 500000;
constexpr float NEG = 0.01f;

__device__ __align__(128) float g_AB[(size_t)NN_MAX * 512];
__device__ __align__(128) float g_red[(size_t)NN_MAX * 128];
__device__ __align__(128) float g_fA[128 * 256];
__device__ __align__(128) float g_fB[128 * 256];
__device__ __align__(128) float g_fC[64 * 256];
__device__ __align__(128) float g_fN1[256 * 256];
__device__ __align__(128) float g_fN2[256 * 128];
__device__ __align__(128) float g_fE2[256 * 128];

__device__ __forceinline__ float lky(float x) { return x >= 0.0f ? x : NEG * x; }

__device__ __forceinline__ float rna_tf32(float x) {
    float r; asm("cvt.rna.tf32.f32 %0, %1;" : "=f"(r) : "f"(x)); return r;
}

__device__ __forceinline__ void red_add_v4(float* addr, float a, float b, float c, float d) {
    asm volatile("red.global.add.v4.f32 [%0], {%1,%2,%3,%4};"
                 :: "l"(addr), "f"(a), "f"(b), "f"(c), "f"(d) : "memory");
}

#define MMA_TF32(D0, D1, D2, D3, AV, AV8, BV)                                   \
    asm volatile("mma.sync.aligned.m16n8k8.row.col.f32.tf32.tf32.f32 "          \
                 "{%0,%1,%2,%3}, {%4,%5,%6,%7}, {%8,%9}, {%0,%1,%2,%3};"        \
                 : "+f"(D0), "+f"(D1), "+f"(D2), "+f"(D3)                       \
                 : "r"((AV).x), "r"((AV8).x), "r"((AV).y), "r"((AV8).y),        \
                   "r"((BV).x), "r"((BV).y))

// ---- merged one-time setup: zero red + all weight fragment shuffles ----
template <int K, int N>
__device__ __forceinline__ void do_frag(int fi, const float* __restrict__ W,
                                        float* __restrict__ Wf) {
    if (fi >= K * N) return;
    int j = fi & 1;
    int lane = (fi >> 1) & 31;
    int kt = (fi >> 6) % (K / 8);
    int ntg = fi / (64 * (K / 8));
    int fc = lane & 3, fg = lane >> 2;
    Wf[fi] = rna_tf32(W[(kt * 8 + 2 * fc + j) * N + ntg * 8 + fg]);
}

__global__ void setup_all(const float* __restrict__ We1, const float* __restrict__ We2,
                          const float* __restrict__ Wn1, const float* __restrict__ Wn2,
                          float4* __restrict__ red4, int n4,
                          float* fA, float* fB, float* fC,
                          float* fN1, float* fN2, float* fE2) {
    int tid = blockIdx.x * 256 + threadIdx.x;
    if (tid < n4) red4[tid] = make_float4(0.f, 0.f, 0.f, 0.f);
    do_frag<128, 256>(tid, We1, fA);
    do_frag<128, 256>(tid, We1 + 128 * 256, fB);
    do_frag<64, 256>(tid, We1 + 256 * 256, fC);
    do_frag<256, 256>(tid, Wn1, fN1);
    do_frag<256, 128>(tid, Wn2, fN2);
    do_frag<256, 128>(tid, We2, fE2);
}

// ---- fused A|B GEMM: g_AB[row] = [nf@We1_A | nf@We1_B], K=128, 2 x N=256 ----
__global__ void __launch_bounds__(256, 2)
mma_gemm_ab(const float* __restrict__ nf, const float* __restrict__ fA,
            const float* __restrict__ fB, float* __restrict__ out, int M) {
    constexpr int ST = 136;
    extern __shared__ float xs[];    // 64 * 136

    const int tid = threadIdx.x;
    const int row0 = blockIdx.x * 64;

    for (int idx = tid; idx < 64 * 32; idx += 256) {
        int r = idx >> 5, k4 = idx & 31;
        int row = row0 + r;
        float4 v = make_float4(0.f, 0.f, 0.f, 0.f);
        if (row < M) v = ((const float4*)nf)[(size_t)row * 32 + k4];
        v.x = rna_tf32(v.x); v.y = rna_tf32(v.y);
        v.z = rna_tf32(v.z); v.w = rna_tf32(v.w);
        *(float4*)&xs[r * ST + k4 * 4] = v;
    }
    __syncthreads();

    const int w = tid >> 5, lane = tid & 31;
    const int fg = lane >> 2, fc = lane & 3;

#pragma unroll
    for (int h2 = 0; h2 < 2; h2++) {
        const float* Wf = h2 ? fB : fA;
        float d0[4][4], d1[4][4], d2[4][4], d3[4][4];
#pragma unroll
        for (int mt = 0; mt < 4; mt++)
#pragma unroll
            for (int nt = 0; nt < 4; nt++) { d0[mt][nt] = d1[mt][nt] = d2[mt][nt] = d3[mt][nt] = 0.f; }

        for (int kt = 0; kt < 16; kt++) {
            uint2 a[8];
#pragma unroll
            for (int j = 0; j < 8; j++)
                a[j] = *(const uint2*)&xs[(fg + j * 8) * ST + kt * 8 + 2 * fc];
#pragma unroll
            for (int nt = 0; nt < 4; nt++) {
                uint2 bv = __ldg((const uint2*)&Wf[(size_t)((w * 4 + nt) * 16 + kt) * 64 + lane * 2]);
#pragma unroll
                for (int mt = 0; mt < 4; mt++)
                    MMA_TF32(d0[mt][nt], d1[mt][nt], d2[mt][nt], d3[mt][nt],
                             a[2 * mt], a[2 * mt + 1], bv);
            }
        }

#pragma unroll
        for (int mt = 0; mt < 4; mt++) {
#pragma unroll
            for (int nt = 0; nt < 4; nt++) {
                int row = row0 + mt * 16 + fg;
                int col = h2 * 256 + w * 32 + nt * 8 + 2 * fc;
                if (row < M)     *(float2*)&out[(size_t)row * 512 + col]       = make_float2(d0[mt][nt], d1[mt][nt]);
                if (row + 8 < M) *(float2*)&out[(size_t)(row + 8) * 512 + col] = make_float2(d2[mt][nt], d3[mt][nt]);
            }
        }
    }
}

// ---- fused edge kernel: tile = 32 edges -> 64 edge-dir rows ----
constexpr int EST = 264;
constexpr int EFST = 68;                               // padded ef smem row stride
constexpr int EFS_OFF = 64 * EST;                      // float offset of ef tile in smem
constexpr int SM_EDGE = (64 * EST + 32 * EFST) * 4;    // 76288 B

__global__ void __launch_bounds__(256, 3)
edge_fused(const float* __restrict__ AB, const float* __restrict__ ef,
           const float* __restrict__ fC, const float* __restrict__ fE2,
           const int* __restrict__ src, const int* __restrict__ dst,
           float* __restrict__ red, int E) {
    extern __shared__ float hs[];   // [0,64*264): h rows; [EFS_OFF, +32*68): ef tile
    float* efs = hs + EFS_OFF;
    __shared__ int ss[64], dds[64];

    const int tid = threadIdx.x;
    const int t = blockIdx.x;

    if (tid < 64) {
        int er = tid >> 1;
        bool rev = tid & 1;
        int e = t * 32 + er;
        int sv = -1, dv = -1;
        if (e < E) { sv = src[e]; dv = dst[e]; }
        ss[tid]  = rev ? dv : sv;
        dds[tid] = rev ? sv : dv;
    }

    const int w = tid >> 5, lane = tid & 31;
    const int fg = lane >> 2, fc = lane & 3;

    // ---- stage ef tile (contiguous 8 KB) -> smem, coalesced ----
    {
        const int maxe = E - t * 32;
        const float4* eft = (const float4*)(ef + (size_t)t * 32 * 64);
#pragma unroll
        for (int it = 0; it < 2; it++) {
            int idx = tid + it * 256;           // 0..511 = 32 rows x 16 float4
            int r = idx >> 4, c4 = idx & 15;
            float4 v = make_float4(0.f, 0.f, 0.f, 0.f);
            if (r < maxe) v = eft[idx];
            *(float4*)&efs[r * EFST + c4 * 4] = v;
        }
    }
    __syncthreads();

    // ---- phase 1a: C mma (M=32, K=64) once per edge; store RAW D into even hs rows ----
#pragma unroll
    for (int ch = 0; ch < 2; ch++) {           // per-warp NT=4, chunks of 2
        float d0[2][2], d1[2][2], d2[2][2], d3[2][2];
#pragma unroll
        for (int mt = 0; mt < 2; mt++)
#pragma unroll
            for (int nt = 0; nt < 2; nt++) { d0[mt][nt] = d1[mt][nt] = d2[mt][nt] = d3[mt][nt] = 0.f; }

#pragma unroll
        for (int kt = 0; kt < 8; kt++) {
            uint2 a[4];
#pragma unroll
            for (int j = 0; j < 4; j++)
                a[j] = *(const uint2*)&efs[(fg + j * 8) * EFST + kt * 8 + 2 * fc];
#pragma unroll
            for (int nt = 0; nt < 2; nt++) {
                int ntg = w * 4 + ch * 2 + nt;
                uint2 bv = __ldg((const uint2*)&fC[(size_t)(ntg * 8 + kt) * 64 + lane * 2]);
#pragma unroll
                for (int mt = 0; mt < 2; mt++)
                    MMA_TF32(d0[mt][nt], d1[mt][nt], d2[mt][nt], d3[mt][nt],
                             a[2 * mt], a[2 * mt + 1], bv);
            }
        }

        // store raw C fragments into even hs rows (row 2*er, cols of this warp)
#pragma unroll
        for (int mt = 0; mt < 2; mt++) {
#pragma unroll
            for (int nt = 0; nt < 2; nt++) {
                int col = w * 32 + (ch * 2 + nt) * 8 + 2 * fc;
#pragma unroll
                for (int half = 0; half < 2; half++) {
                    int er = mt * 16 + fg + half * 8;          // edge row 0..31
                    float cx = half ? d2[mt][nt] : d0[mt][nt];
                    float cy = half ? d3[mt][nt] : d1[mt][nt];
                    *(float2*)&hs[(2 * er) * EST + col] = make_float2(cx, cy);
                }
            }
        }
    }
    __syncthreads();

    // ---- phase 1b: pair-fused gather; warp w owns edge pairs w*4..w*4+3 ----
#pragma unroll
    for (int i = 0; i < 4; i++) {
        const int er = w * 4 + i;
        const int hr = 2 * er;
        const int s = ss[hr], d = dds[hr];

        // read C row (written by all warps) BEFORE overwriting
        float4 c0 = *(const float4*)&hs[hr * EST + lane * 4];
        float4 c1 = *(const float4*)&hs[hr * EST + 128 + lane * 4];

        float4 f0, f1, r0, r1;
        if (s >= 0) {
            const float4* pS = (const float4*)(AB + (size_t)s * 512);
            const float4* pD = (const float4*)(AB + (size_t)d * 512);
            float4 as0 = pS[lane],      as1 = pS[32 + lane];   // A[s]
            float4 bs0 = pS[64 + lane], bs1 = pS[96 + lane];   // B[s]
            float4 ad0 = pD[lane],      ad1 = pD[32 + lane];   // A[d]
            float4 bd0 = pD[64 + lane], bd1 = pD[96 + lane];   // B[d]
            f0.x = rna_tf32(lky(c0.x + as0.x + bd0.x));
            f0.y = rna_tf32(lky(c0.y + as0.y + bd0.y));
            f0.z = rna_tf32(lky(c0.z + as0.z + bd0.z));
            f0.w = rna_tf32(lky(c0.w + as0.w + bd0.w));
            f1.x = rna_tf32(lky(c1.x + as1.x + bd1.x));
            f1.y = rna_tf32(lky(c1.y + as1.y + bd1.y));
            f1.z = rna_tf32(lky(c1.z + as1.z + bd1.z));
            f1.w = rna_tf32(lky(c1.w + as1.w + bd1.w));
            r0.x = rna_tf32(lky(c0.x + ad0.x + bs0.x));
            r0.y = rna_tf32(lky(c0.y + ad0.y + bs0.y));
            r0.z = rna_tf32(lky(c0.z + ad0.z + bs0.z));
            r0.w = rna_tf32(lky(c0.w + ad0.w + bs0.w));
            r1.x = rna_tf32(lky(c1.x + ad1.x + bs1.x));
            r1.y = rna_tf32(lky(c1.y + ad1.y + bs1.y));
            r1.z = rna_tf32(lky(c1.z + ad1.z + bs1.z));
            r1.w = rna_tf32(lky(c1.w + ad1.w + bs1.w));
        } else {
            f0 = f1 = r0 = r1 = make_float4(0.f, 0.f, 0.f, 0.f);
        }
        *(float4*)&hs[hr * EST + lane * 4]             = f0;
        *(float4*)&hs[hr * EST + 128 + lane * 4]       = f1;
        *(float4*)&hs[(hr + 1) * EST + lane * 4]       = r0;
        *(float4*)&hs[(hr + 1) * EST + 128 + lane * 4] = r1;
    }
    __syncthreads();

    // ---- phase 2: msg = h @ We2; 2(M) x 4(N) warp grid, Mw=32, Nw=32 ----
    const int wm = w & 1, wc = w >> 1;
    const int rb = wm * 32;

    float e0[2][4], e1[2][4], e2[2][4], e3[2][4];
#pragma unroll
    for (int mt = 0; mt < 2; mt++)
#pragma unroll
        for (int nt = 0; nt < 4; nt++) { e0[mt][nt] = e1[mt][nt] = e2[mt][nt] = e3[mt][nt] = 0.f; }

    for (int kt = 0; kt < 32; kt++) {
        uint2 a[4];
#pragma unroll
        for (int j = 0; j < 4; j++)
            a[j] = *(const uint2*)&hs[(rb + fg + j * 8) * EST + kt * 8 + 2 * fc];
#pragma unroll
        for (int nt = 0; nt < 4; nt++) {
            uint2 bv = __ldg((const uint2*)&fE2[(size_t)((wc * 4 + nt) * 32 + kt) * 64 + lane * 2]);
#pragma unroll
            for (int mt = 0; mt < 2; mt++)
                MMA_TF32(e0[mt][nt], e1[mt][nt], e2[mt][nt], e3[mt][nt],
                         a[2 * mt], a[2 * mt + 1], bv);
        }
    }

    // ---- scatter-add (v4 via lane pairing) ----
#pragma unroll
    for (int mt = 0; mt < 2; mt++) {
        int rowA = rb + mt * 16 + fg;
        int dA = dds[rowA];
        int dB = dds[rowA + 8];
#pragma unroll
        for (int nt = 0; nt < 4; nt++) {
            float s0 = __shfl_down_sync(0xffffffffu, e0[mt][nt], 1);
            float s1 = __shfl_down_sync(0xffffffffu, e1[mt][nt], 1);
            float s2 = __shfl_down_sync(0xffffffffu, e2[mt][nt], 1);
            float s3 = __shfl_down_sync(0xffffffffu, e3[mt][nt], 1);
            if ((fc & 1) == 0) {
                int col = wc * 32 + nt * 8 + 2 * fc;
                if (dA >= 0) red_add_v4(&red[(size_t)dA * 128 + col], e0[mt][nt], e1[mt][nt], s0, s1);
                if (dB >= 0) red_add_v4(&red[(size_t)dB * 128 + col], e2[mt][nt], e3[mt][nt], s2, s3);
            }
        }
    }
}

// ---- fused node MLP: hn = leaky([nf|red] @ Wn1); out = hn @ Wn2 ----
__global__ void __launch_bounds__(256, 2)
node_fused(const float* __restrict__ nf, const float* __restrict__ red,
           const float* __restrict__ fN1, const float* __restrict__ fN2,
           float* __restrict__ out, int M) {
    extern __shared__ float xs[];   // 64 * 264
    const int tid = threadIdx.x;
    const int row0 = blockIdx.x * 64;

    for (int idx = tid; idx < 64 * 64; idx += 256) {
        int r = idx >> 6, k4 = idx & 63;
        int row = row0 + r;
        float4 v = make_float4(0.f, 0.f, 0.f, 0.f);
        if (row < M)
            v = (k4 < 32) ? ((const float4*)nf)[(size_t)row * 32 + k4]
                          : ((const float4*)red)[(size_t)row * 32 + (k4 - 32)];
        v.x = rna_tf32(v.x); v.y = rna_tf32(v.y);
        v.z = rna_tf32(v.z); v.w = rna_tf32(v.w);
        *(float4*)&xs[r * EST + k4 * 4] = v;
    }
    __syncthreads();

    const int w = tid >> 5, lane = tid & 31;
    const int fg = lane >> 2, fc = lane & 3;

    float h0[4][4], h1[4][4], h2[4][4], h3[4][4];
#pragma unroll
    for (int mt = 0; mt < 4; mt++)
#pragma unroll
        for (int nt = 0; nt < 4; nt++) { h0[mt][nt] = h1[mt][nt] = h2[mt][nt] = h3[mt][nt] = 0.f; }

    for (int kt = 0; kt < 32; kt++) {
        uint2 a[8];
#pragma unroll
        for (int j = 0; j < 8; j++)
            a[j] = *(const uint2*)&xs[(fg + j * 8) * EST + kt * 8 + 2 * fc];
#pragma unroll
        for (int nt = 0; nt < 4; nt++) {
            uint2 bv = __ldg((const uint2*)&fN1[(size_t)((w * 4 + nt) * 32 + kt) * 64 + lane * 2]);
#pragma unroll
            for (int mt = 0; mt < 4; mt++)
                MMA_TF32(h0[mt][nt], h1[mt][nt], h2[mt][nt], h3[mt][nt],
                         a[2 * mt], a[2 * mt + 1], bv);
        }
    }
    __syncthreads();

#pragma unroll
    for (int mt = 0; mt < 4; mt++) {
#pragma unroll
        for (int nt = 0; nt < 4; nt++) {
            int row = mt * 16 + fg;
            int col = w * 32 + nt * 8 + 2 * fc;
            *(float2*)&xs[row * EST + col] =
                make_float2(rna_tf32(lky(h0[mt][nt])), rna_tf32(lky(h1[mt][nt])));
            *(float2*)&xs[(row + 8) * EST + col] =
                make_float2(rna_tf32(lky(h2[mt][nt])), rna_tf32(lky(h3[mt][nt])));
        }
    }
    __syncthreads();

    float o0[4][2], o1[4][2], o2[4][2], o3[4][2];
#pragma unroll
    for (int mt = 0; mt < 4; mt++)
#pragma unroll
        for (int nt = 0; nt < 2; nt++) { o0[mt][nt] = o1[mt][nt] = o2[mt][nt] = o3[mt][nt] = 0.f; }

    for (int kt = 0; kt < 32; kt++) {
        uint2 a[8];
#pragma unroll
        for (int j = 0; j < 8; j++)
            a[j] = *(const uint2*)&xs[(fg + j * 8) * EST + kt * 8 + 2 * fc];
#pragma unroll
        for (int nt = 0; nt < 2; nt++) {
            uint2 bv = __ldg((const uint2*)&fN2[(size_t)((w * 2 + nt) * 32 + kt) * 64 + lane * 2]);
#pragma unroll
            for (int mt = 0; mt < 4; mt++)
                MMA_TF32(o0[mt][nt], o1[mt][nt], o2[mt][nt], o3[mt][nt],
                         a[2 * mt], a[2 * mt + 1], bv);
        }
    }

#pragma unroll
    for (int mt = 0; mt < 4; mt++) {
#pragma unroll
        for (int nt = 0; nt < 2; nt++) {
            int row = row0 + mt * 16 + fg;
            int col = w * 16 + nt * 8 + 2 * fc;
            if (row < M)     *(float2*)&out[(size_t)row * 128 + col]       = make_float2(o0[mt][nt], o1[mt][nt]);
            if (row + 8 < M) *(float2*)&out[(size_t)(row + 8) * 128 + col] = make_float2(o2[mt][nt], o3[mt][nt]);
        }
    }
}

extern "C" void kernel_launch(void* const* d_in, const int* in_sizes, int n_in,
                              void* d_out, int out_size) {
    const float* nf  = (const float*)d_in[0];
    const float* ef  = (const float*)d_in[1];
    const int*   src = (const int*)d_in[2];
    const int*   dst = (const int*)d_in[3];
    const float* We1 = (const float*)d_in[4];   // (320, 256)
    const float* We2 = (const float*)d_in[5];   // (256, 128)
    const float* Wn1 = (const float*)d_in[6];   // (256, 256)
    const float* Wn2 = (const float*)d_in[7];   // (256, 128)

    const int N = in_sizes[0] / 128;
    const int E = in_sizes[2];

    float *AB, *red, *fA, *fB, *fC, *fN1, *fN2, *fE2;
    cudaGetSymbolAddress((void**)&AB, g_AB);
    cudaGetSymbolAddress((void**)&red, g_red);
    cudaGetSymbolAddress((void**)&fA, g_fA);
    cudaGetSymbolAddress((void**)&fB, g_fB);
    cudaGetSymbolAddress((void**)&fC, g_fC);
    cudaGetSymbolAddress((void**)&fN1, g_fN1);
    cudaGetSymbolAddress((void**)&fN2, g_fN2);
    cudaGetSymbolAddress((void**)&fE2, g_fE2);

    cudaFuncSetAttribute((const void*)edge_fused,
                         cudaFuncAttributeMaxDynamicSharedMemorySize, SM_EDGE);
    cudaFuncSetAttribute((const void*)node_fused,
                         cudaFuncAttributeMaxDynamicSharedMemorySize, 64 * EST * 4);

    // (0) merged one-time setup: zero red + all weight fragment shuffles
    int n4 = N * 128 / 4;
    setup_all<<<(n4 + 255) / 256, 256>>>(We1, We2, Wn1, Wn2,
                                         (float4*)red, n4, fA, fB, fC, fN1, fN2, fE2);

    // (1) fused A|B: nf @ We1 halves -> g_AB (row stride 512)
    mma_gemm_ab<<<(N + 63) / 64, 256, 64 * 136 * 4>>>(nf, fA, fB, AB, N);

    // (2) fused edge: staged ef + C mma -> hs + pair-fused gather + msg mma + scatter
    edge_fused<<<(E + 31) / 32, 256, SM_EDGE>>>(AB, ef, fC, fE2, src, dst, red, E);

    // (3) fused node MLP
    node_fused<<<(N + 63) / 64, 256, 64 * EST * 4>>>(nf, red, fN1, fN2, (float*)d_out, N);
}

// round 13
// speedup vs baseline: 2.1017x; 1.0396x over previous
#include <cuda_runtime.h>
#include <cstdint>

// GNN layer, all GEMMs on tf32 mma.sync m16n8k8:
//   A|B = nf @ We1 halves (per node, one fused kernel)
//   edge (fused): ef tile staged -> smem; Cfrag = ef @ We1_ef (mma, M=32, once/edge),
//                 D-frags stored RAW into even hs rows;
//                 pair-fused gather: h_fwd/h_rev = rna(leaky(C + A/B combos)) -> hs;
//                 msg = h @ We2 (mma, 2Mx4N); D staged to hs; ROW-COALESCED red.global.add.v4
//   node (fused): hn = leaky([nf|red] @ Wn1) -> smem; out = hn @ Wn2
// Weight fragments pre-shuffled (coalesced LDG.64 B-frags):
//   Wf[((ntg*(K/8)+kt)*64 + lane*2 + j)] = rna(W[(kt*8+2*(lane&3)+j)*N + ntg*8 + (lane>>2)])

constexpr int NN_MAX = 100000;
constexpr int NE_MAX = 500000;
constexpr float NEG = 0.01f;

__device__ __align__(128) float g_AB[(size_t)NN_MAX * 512];
__device__ __align__(128) float g_red[(size_t)NN_MAX * 128];
__device__ __align__(128) float g_fA[128 * 256];
__device__ __align__(128) float g_fB[128 * 256];
__device__ __align__(128) float g_fC[64 * 256];
__device__ __align__(128) float g_fN1[256 * 256];
__device__ __align__(128) float g_fN2[256 * 128];
__device__ __align__(128) float g_fE2[256 * 128];

__device__ __forceinline__ float lky(float x) { return x >= 0.0f ? x : NEG * x; }

__device__ __forceinline__ float rna_tf32(float x) {
    float r; asm("cvt.rna.tf32.f32 %0, %1;" : "=f"(r) : "f"(x)); return r;
}

__device__ __forceinline__ void red_add_v4(float* addr, float a, float b, float c, float d) {
    asm volatile("red.global.add.v4.f32 [%0], {%1,%2,%3,%4};"
                 :: "l"(addr), "f"(a), "f"(b), "f"(c), "f"(d) : "memory");
}

#define MMA_TF32(D0, D1, D2, D3, AV, AV8, BV)                                   \
    asm volatile("mma.sync.aligned.m16n8k8.row.col.f32.tf32.tf32.f32 "          \
                 "{%0,%1,%2,%3}, {%4,%5,%6,%7}, {%8,%9}, {%0,%1,%2,%3};"        \
                 : "+f"(D0), "+f"(D1), "+f"(D2), "+f"(D3)                       \
                 : "r"((AV).x), "r"((AV8).x), "r"((AV).y), "r"((AV8).y),        \
                   "r"((BV).x), "r"((BV).y))

// ---- merged one-time setup: zero red + all weight fragment shuffles ----
template <int K, int N>
__device__ __forceinline__ void do_frag(int fi, const float* __restrict__ W,
                                        float* __restrict__ Wf) {
    if (fi >= K * N) return;
    int j = fi & 1;
    int lane = (fi >> 1) & 31;
    int kt = (fi >> 6) % (K / 8);
    int ntg = fi / (64 * (K / 8));
    int fc = lane & 3, fg = lane >> 2;
    Wf[fi] = rna_tf32(W[(kt * 8 + 2 * fc + j) * N + ntg * 8 + fg]);
}

__global__ void setup_all(const float* __restrict__ We1, const float* __restrict__ We2,
                          const float* __restrict__ Wn1, const float* __restrict__ Wn2,
                          float4* __restrict__ red4, int n4,
                          float* fA, float* fB, float* fC,
                          float* fN1, float* fN2, float* fE2) {
    int tid = blockIdx.x * 256 + threadIdx.x;
    if (tid < n4) red4[tid] = make_float4(0.f, 0.f, 0.f, 0.f);
    do_frag<128, 256>(tid, We1, fA);
    do_frag<128, 256>(tid, We1 + 128 * 256, fB);
    do_frag<64, 256>(tid, We1 + 256 * 256, fC);
    do_frag<256, 256>(tid, Wn1, fN1);
    do_frag<256, 128>(tid, Wn2, fN2);
    do_frag<256, 128>(tid, We2, fE2);
}

// ---- fused A|B GEMM: g_AB[row] = [nf@We1_A | nf@We1_B], K=128, 2 x N=256 ----
__global__ void __launch_bounds__(256, 2)
mma_gemm_ab(const float* __restrict__ nf, const float* __restrict__ fA,
            const float* __restrict__ fB, float* __restrict__ out, int M) {
    constexpr int ST = 136;
    extern __shared__ float xs[];    // 64 * 136

    const int tid = threadIdx.x;
    const int row0 = blockIdx.x * 64;

    for (int idx = tid; idx < 64 * 32; idx += 256) {
        int r = idx >> 5, k4 = idx & 31;
        int row = row0 + r;
        float4 v = make_float4(0.f, 0.f, 0.f, 0.f);
        if (row < M) v = ((const float4*)nf)[(size_t)row * 32 + k4];
        v.x = rna_tf32(v.x); v.y = rna_tf32(v.y);
        v.z = rna_tf32(v.z); v.w = rna_tf32(v.w);
        *(float4*)&xs[r * ST + k4 * 4] = v;
    }
    __syncthreads();

    const int w = tid >> 5, lane = tid & 31;
    const int fg = lane >> 2, fc = lane & 3;

#pragma unroll
    for (int h2 = 0; h2 < 2; h2++) {
        const float* Wf = h2 ? fB : fA;
        float d0[4][4], d1[4][4], d2[4][4], d3[4][4];
#pragma unroll
        for (int mt = 0; mt < 4; mt++)
#pragma unroll
            for (int nt = 0; nt < 4; nt++) { d0[mt][nt] = d1[mt][nt] = d2[mt][nt] = d3[mt][nt] = 0.f; }

        for (int kt = 0; kt < 16; kt++) {
            uint2 a[8];
#pragma unroll
            for (int j = 0; j < 8; j++)
                a[j] = *(const uint2*)&xs[(fg + j * 8) * ST + kt * 8 + 2 * fc];
#pragma unroll
            for (int nt = 0; nt < 4; nt++) {
                uint2 bv = __ldg((const uint2*)&Wf[(size_t)((w * 4 + nt) * 16 + kt) * 64 + lane * 2]);
#pragma unroll
                for (int mt = 0; mt < 4; mt++)
                    MMA_TF32(d0[mt][nt], d1[mt][nt], d2[mt][nt], d3[mt][nt],
                             a[2 * mt], a[2 * mt + 1], bv);
            }
        }

#pragma unroll
        for (int mt = 0; mt < 4; mt++) {
#pragma unroll
            for (int nt = 0; nt < 4; nt++) {
                int row = row0 + mt * 16 + fg;
                int col = h2 * 256 + w * 32 + nt * 8 + 2 * fc;
                if (row < M)     *(float2*)&out[(size_t)row * 512 + col]       = make_float2(d0[mt][nt], d1[mt][nt]);
                if (row + 8 < M) *(float2*)&out[(size_t)(row + 8) * 512 + col] = make_float2(d2[mt][nt], d3[mt][nt]);
            }
        }
    }
}

// ---- fused edge kernel: tile = 32 edges -> 64 edge-dir rows ----
constexpr int EST = 264;
constexpr int EFST = 68;                               // padded ef smem row stride
constexpr int EFS_OFF = 64 * EST;                      // float offset of ef tile in smem
constexpr int SM_EDGE = (64 * EST + 32 * EFST) * 4;    // 76288 B

__global__ void __launch_bounds__(256, 3)
edge_fused(const float* __restrict__ AB, const float* __restrict__ ef,
           const float* __restrict__ fC, const float* __restrict__ fE2,
           const int* __restrict__ src, const int* __restrict__ dst,
           float* __restrict__ red, int E) {
    extern __shared__ float hs[];   // [0,64*264): h rows; [EFS_OFF, +32*68): ef tile
    float* efs = hs + EFS_OFF;
    __shared__ int ss[64], dds[64];

    const int tid = threadIdx.x;
    const int t = blockIdx.x;

    if (tid < 64) {
        int er = tid >> 1;
        bool rev = tid & 1;
        int e = t * 32 + er;
        int sv = -1, dv = -1;
        if (e < E) { sv = src[e]; dv = dst[e]; }
        ss[tid]  = rev ? dv : sv;
        dds[tid] = rev ? sv : dv;
    }

    const int w = tid >> 5, lane = tid & 31;
    const int fg = lane >> 2, fc = lane & 3;

    // ---- stage ef tile (contiguous 8 KB) -> smem, coalesced ----
    {
        const int maxe = E - t * 32;
        const float4* eft = (const float4*)(ef + (size_t)t * 32 * 64);
#pragma unroll
        for (int it = 0; it < 2; it++) {
            int idx = tid + it * 256;           // 0..511 = 32 rows x 16 float4
            int r = idx >> 4, c4 = idx & 15;
            float4 v = make_float4(0.f, 0.f, 0.f, 0.f);
            if (r < maxe) v = eft[idx];
            *(float4*)&efs[r * EFST + c4 * 4] = v;
        }
    }
    __syncthreads();

    // ---- phase 1a: C mma (M=32, K=64) once per edge; store RAW D into even hs rows ----
#pragma unroll
    for (int ch = 0; ch < 2; ch++) {           // per-warp NT=4, chunks of 2
        float d0[2][2], d1[2][2], d2[2][2], d3[2][2];
#pragma unroll
        for (int mt = 0; mt < 2; mt++)
#pragma unroll
            for (int nt = 0; nt < 2; nt++) { d0[mt][nt] = d1[mt][nt] = d2[mt][nt] = d3[mt][nt] = 0.f; }

#pragma unroll
        for (int kt = 0; kt < 8; kt++) {
            uint2 a[4];
#pragma unroll
            for (int j = 0; j < 4; j++)
                a[j] = *(const uint2*)&efs[(fg + j * 8) * EFST + kt * 8 + 2 * fc];
#pragma unroll
            for (int nt = 0; nt < 2; nt++) {
                int ntg = w * 4 + ch * 2 + nt;
                uint2 bv = __ldg((const uint2*)&fC[(size_t)(ntg * 8 + kt) * 64 + lane * 2]);
#pragma unroll
                for (int mt = 0; mt < 2; mt++)
                    MMA_TF32(d0[mt][nt], d1[mt][nt], d2[mt][nt], d3[mt][nt],
                             a[2 * mt], a[2 * mt + 1], bv);
            }
        }

        // store raw C fragments into even hs rows (row 2*er, cols of this warp)
#pragma unroll
        for (int mt = 0; mt < 2; mt++) {
#pragma unroll
            for (int nt = 0; nt < 2; nt++) {
                int col = w * 32 + (ch * 2 + nt) * 8 + 2 * fc;
#pragma unroll
                for (int half = 0; half < 2; half++) {
                    int er = mt * 16 + fg + half * 8;          // edge row 0..31
                    float cx = half ? d2[mt][nt] : d0[mt][nt];
                    float cy = half ? d3[mt][nt] : d1[mt][nt];
                    *(float2*)&hs[(2 * er) * EST + col] = make_float2(cx, cy);
                }
            }
        }
    }
    __syncthreads();

    // ---- phase 1b: pair-fused gather; warp w owns edge pairs w*4..w*4+3 ----
#pragma unroll
    for (int i = 0; i < 4; i++) {
        const int er = w * 4 + i;
        const int hr = 2 * er;
        const int s = ss[hr], d = dds[hr];

        // read C row (written by all warps) BEFORE overwriting
        float4 c0 = *(const float4*)&hs[hr * EST + lane * 4];
        float4 c1 = *(const float4*)&hs[hr * EST + 128 + lane * 4];

        float4 f0, f1, r0, r1;
        if (s >= 0) {
            const float4* pS = (const float4*)(AB + (size_t)s * 512);
            const float4* pD = (const float4*)(AB + (size_t)d * 512);
            float4 as0 = pS[lane],      as1 = pS[32 + lane];   // A[s]
            float4 bs0 = pS[64 + lane], bs1 = pS[96 + lane];   // B[s]
            float4 ad0 = pD[lane],      ad1 = pD[32 + lane];   // A[d]
            float4 bd0 = pD[64 + lane], bd1 = pD[96 + lane];   // B[d]
            f0.x = rna_tf32(lky(c0.x + as0.x + bd0.x));
            f0.y = rna_tf32(lky(c0.y + as0.y + bd0.y));
            f0.z = rna_tf32(lky(c0.z + as0.z + bd0.z));
            f0.w = rna_tf32(lky(c0.w + as0.w + bd0.w));
            f1.x = rna_tf32(lky(c1.x + as1.x + bd1.x));
            f1.y = rna_tf32(lky(c1.y + as1.y + bd1.y));
            f1.z = rna_tf32(lky(c1.z + as1.z + bd1.z));
            f1.w = rna_tf32(lky(c1.w + as1.w + bd1.w));
            r0.x = rna_tf32(lky(c0.x + ad0.x + bs0.x));
            r0.y = rna_tf32(lky(c0.y + ad0.y + bs0.y));
            r0.z = rna_tf32(lky(c0.z + ad0.z + bs0.z));
            r0.w = rna_tf32(lky(c0.w + ad0.w + bs0.w));
            r1.x = rna_tf32(lky(c1.x + ad1.x + bs1.x));
            r1.y = rna_tf32(lky(c1.y + ad1.y + bs1.y));
            r1.z = rna_tf32(lky(c1.z + ad1.z + bs1.z));
            r1.w = rna_tf32(lky(c1.w + ad1.w + bs1.w));
        } else {
            f0 = f1 = r0 = r1 = make_float4(0.f, 0.f, 0.f, 0.f);
        }
        *(float4*)&hs[hr * EST + lane * 4]             = f0;
        *(float4*)&hs[hr * EST + 128 + lane * 4]       = f1;
        *(float4*)&hs[(hr + 1) * EST + lane * 4]       = r0;
        *(float4*)&hs[(hr + 1) * EST + 128 + lane * 4] = r1;
    }
    __syncthreads();

    // ---- phase 2: msg = h @ We2; 2(M) x 4(N) warp grid, Mw=32, Nw=32 ----
    const int wm = w & 1, wc = w >> 1;
    const int rb = wm * 32;

    float e0[2][4], e1[2][4], e2[2][4], e3[2][4];
#pragma unroll
    for (int mt = 0; mt < 2; mt++)
#pragma unroll
        for (int nt = 0; nt < 4; nt++) { e0[mt][nt] = e1[mt][nt] = e2[mt][nt] = e3[mt][nt] = 0.f; }

    for (int kt = 0; kt < 32; kt++) {
        uint2 a[4];
#pragma unroll
        for (int j = 0; j < 4; j++)
            a[j] = *(const uint2*)&hs[(rb + fg + j * 8) * EST + kt * 8 + 2 * fc];
#pragma unroll
        for (int nt = 0; nt < 4; nt++) {
            uint2 bv = __ldg((const uint2*)&fE2[(size_t)((wc * 4 + nt) * 32 + kt) * 64 + lane * 2]);
#pragma unroll
            for (int mt = 0; mt < 2; mt++)
                MMA_TF32(e0[mt][nt], e1[mt][nt], e2[mt][nt], e3[mt][nt],
                         a[2 * mt], a[2 * mt + 1], bv);
        }
    }
    __syncthreads();   // all hs reads done before D staging overwrites

    // ---- stage D frags to hs (conflict-free STS.64) ----
#pragma unroll
    for (int mt = 0; mt < 2; mt++) {
#pragma unroll
        for (int nt = 0; nt < 4; nt++) {
            int row = rb + mt * 16 + fg;
            int col = wc * 32 + nt * 8 + 2 * fc;
            *(float2*)&hs[row * EST + col]       = make_float2(e0[mt][nt], e1[mt][nt]);
            *(float2*)&hs[(row + 8) * EST + col] = make_float2(e2[mt][nt], e3[mt][nt]);
        }
    }
    __syncthreads();

    // ---- row-coalesced scatter: warp w scatters rows w*8..w*8+7 ----
#pragma unroll
    for (int i = 0; i < 8; i++) {
        int row = w * 8 + i;
        int dn = dds[row];
        if (dn >= 0) {
            float4 v = *(const float4*)&hs[row * EST + lane * 4];
            red_add_v4(&red[(size_t)dn * 128 + lane * 4], v.x, v.y, v.z, v.w);
        }
    }
}

// ---- fused node MLP: hn = leaky([nf|red] @ Wn1); out = hn @ Wn2 ----
__global__ void __launch_bounds__(256, 2)
node_fused(const float* __restrict__ nf, const float* __restrict__ red,
           const float* __restrict__ fN1, const float* __restrict__ fN2,
           float* __restrict__ out, int M) {
    extern __shared__ float xs[];   // 64 * 264
    const int tid = threadIdx.x;
    const int row0 = blockIdx.x * 64;

    for (int idx = tid; idx < 64 * 64; idx += 256) {
        int r = idx >> 6, k4 = idx & 63;
        int row = row0 + r;
        float4 v = make_float4(0.f, 0.f, 0.f, 0.f);
        if (row < M)
            v = (k4 < 32) ? ((const float4*)nf)[(size_t)row * 32 + k4]
                          : ((const float4*)red)[(size_t)row * 32 + (k4 - 32)];
        v.x = rna_tf32(v.x); v.y = rna_tf32(v.y);
        v.z = rna_tf32(v.z); v.w = rna_tf32(v.w);
        *(float4*)&xs[r * EST + k4 * 4] = v;
    }
    __syncthreads();

    const int w = tid >> 5, lane = tid & 31;
    const int fg = lane >> 2, fc = lane & 3;

    float h0[4][4], h1[4][4], h2[4][4], h3[4][4];
#pragma unroll
    for (int mt = 0; mt < 4; mt++)
#pragma unroll
        for (int nt = 0; nt < 4; nt++) { h0[mt][nt] = h1[mt][nt] = h2[mt][nt] = h3[mt][nt] = 0.f; }

    for (int kt = 0; kt < 32; kt++) {
        uint2 a[8];
#pragma unroll
        for (int j = 0; j < 8; j++)
            a[j] = *(const uint2*)&xs[(fg + j * 8) * EST + kt * 8 + 2 * fc];
#pragma unroll
        for (int nt = 0; nt < 4; nt++) {
            uint2 bv = __ldg((const uint2*)&fN1[(size_t)((w * 4 + nt) * 32 + kt) * 64 + lane * 2]);
#pragma unroll
            for (int mt = 0; mt < 4; mt++)
                MMA_TF32(h0[mt][nt], h1[mt][nt], h2[mt][nt], h3[mt][nt],
                         a[2 * mt], a[2 * mt + 1], bv);
        }
    }
    __syncthreads();

#pragma unroll
    for (int mt = 0; mt < 4; mt++) {
#pragma unroll
        for (int nt = 0; nt < 4; nt++) {
            int row = mt * 16 + fg;
            int col = w * 32 + nt * 8 + 2 * fc;
            *(float2*)&xs[row * EST + col] =
                make_float2(rna_tf32(lky(h0[mt][nt])), rna_tf32(lky(h1[mt][nt])));
            *(float2*)&xs[(row + 8) * EST + col] =
                make_float2(rna_tf32(lky(h2[mt][nt])), rna_tf32(lky(h3[mt][nt])));
        }
    }
    __syncthreads();

    float o0[4][2], o1[4][2], o2[4][2], o3[4][2];
#pragma unroll
    for (int mt = 0; mt < 4; mt++)
#pragma unroll
        for (int nt = 0; nt < 2; nt++) { o0[mt][nt] = o1[mt][nt] = o2[mt][nt] = o3[mt][nt] = 0.f; }

    for (int kt = 0; kt < 32; kt++) {
        uint2 a[8];
#pragma unroll
        for (int j = 0; j < 8; j++)
            a[j] = *(const uint2*)&xs[(fg + j * 8) * EST + kt * 8 + 2 * fc];
#pragma unroll
        for (int nt = 0; nt < 2; nt++) {
            uint2 bv = __ldg((const uint2*)&fN2[(size_t)((w * 2 + nt) * 32 + kt) * 64 + lane * 2]);
#pragma unroll
            for (int mt = 0; mt < 4; mt++)
                MMA_TF32(o0[mt][nt], o1[mt][nt], o2[mt][nt], o3[mt][nt],
                         a[2 * mt], a[2 * mt + 1], bv);
        }
    }

#pragma unroll
    for (int mt = 0; mt < 4; mt++) {
#pragma unroll
        for (int nt = 0; nt < 2; nt++) {
            int row = row0 + mt * 16 + fg;
            int col = w * 16 + nt * 8 + 2 * fc;
            if (row < M)     *(float2*)&out[(size_t)row * 128 + col]       = make_float2(o0[mt][nt], o1[mt][nt]);
            if (row + 8 < M) *(float2*)&out[(size_t)(row + 8) * 128 + col] = make_float2(o2[mt][nt], o3[mt][nt]);
        }
    }
}

extern "C" void kernel_launch(void* const* d_in, const int* in_sizes, int n_in,
                              void* d_out, int out_size) {
    const float* nf  = (const float*)d_in[0];
    const float* ef  = (const float*)d_in[1];
    const int*   src = (const int*)d_in[2];
    const int*   dst = (const int*)d_in[3];
    const float* We1 = (const float*)d_in[4];   // (320, 256)
    const float* We2 = (const float*)d_in[5];   // (256, 128)
    const float* Wn1 = (const float*)d_in[6];   // (256, 256)
    const float* Wn2 = (const float*)d_in[7];   // (256, 128)

    const int N = in_sizes[0] / 128;
    const int E = in_sizes[2];

    float *AB, *red, *fA, *fB, *fC, *fN1, *fN2, *fE2;
    cudaGetSymbolAddress((void**)&AB, g_AB);
    cudaGetSymbolAddress((void**)&red, g_red);
    cudaGetSymbolAddress((void**)&fA, g_fA);
    cudaGetSymbolAddress((void**)&fB, g_fB);
    cudaGetSymbolAddress((void**)&fC, g_fC);
    cudaGetSymbolAddress((void**)&fN1, g_fN1);
    cudaGetSymbolAddress((void**)&fN2, g_fN2);
    cudaGetSymbolAddress((void**)&fE2, g_fE2);

    cudaFuncSetAttribute((const void*)edge_fused,
                         cudaFuncAttributeMaxDynamicSharedMemorySize, SM_EDGE);
    cudaFuncSetAttribute((const void*)node_fused,
                         cudaFuncAttributeMaxDynamicSharedMemorySize, 64 * EST * 4);

    // (0) merged one-time setup: zero red + all weight fragment shuffles
    int n4 = N * 128 / 4;
    setup_all<<<(n4 + 255) / 256, 256>>>(We1, We2, Wn1, Wn2,
                                         (float4*)red, n4, fA, fB, fC, fN1, fN2, fE2);

    // (1) fused A|B: nf @ We1 halves -> g_AB (row stride 512)
    mma_gemm_ab<<<(N + 63) / 64, 256, 64 * 136 * 4>>>(nf, fA, fB, AB, N);

    // (2) fused edge: staged ef + C mma -> hs + pair-fused gather + msg mma + coalesced scatter
    edge_fused<<<(E + 31) / 32, 256, SM_EDGE>>>(AB, ef, fC, fE2, src, dst, red, E);

    // (3) fused node MLP
    node_fused<<<(N + 63) / 64, 256, 64 * EST * 4>>>(nf, red, fN1, fN2, (float*)d_out, N);
}